// round 2
// baseline (speedup 1.0000x reference)
#include <cuda_runtime.h>
#include <math.h>

#define BB 2
#define TT 2048
#define CC 1024
#define HH 16
#define HD 64
#define NBH (BB*HH)          // 32
#define C3 (3*CC)            // 3072

// ---------------- device scratch (allocation-free) ----------------
__device__ float g_q[BB*HH*TT*HD];     // 4.19M floats, [bh][t][d]
__device__ float g_k[BB*HH*TT*HD];
__device__ float g_v[BB*HH*TT*HD];
__device__ float g_o[BB*HH*TT*HD];     // attention output, [bh][t][d]
__device__ float g_rmax[BB*HH*TT];
__device__ float g_rinv[BB*HH*TT];
__device__ float g_cos[TT*32];
__device__ float g_sin[TT*32];

// ---------------- RoPE table (double precision, fp32 theta rounding like reference) ----
__global__ void k_rope_tab() {
    int idx = blockIdx.x * 256 + threadIdx.x;
    if (idx >= TT * 32) return;
    int t = idx / 32, j = idx % 32;
    int mi = (2 * j) % 32;                       // inv_freq column used by pair j
    // best fp32 estimate of reference's inv_freq, then fp32 product (as reference does),
    // then accurate trig on that exact fp32 angle.
    float inv32 = (float)pow(10000.0, -(double)mi / 32.0);
    float th32  = (float)t * inv32;
    g_cos[idx] = (float)cos((double)th32);
    g_sin[idx] = (float)sin((double)th32);
}

// ---------------- K1: QKV GEMM (4096 x 3072 x 1024) + RoPE + scatter ----------------
__global__ __launch_bounds__(256) void k_qkv_rope(const float* __restrict__ x,
                                                  const float* __restrict__ Wqkv) {
    __shared__ float As[64][17];
    __shared__ float Bs[16][68];
    const int tid = threadIdx.x;
    const int tx = tid & 15, ty = tid >> 4;
    const int bm = blockIdx.y * 64, bn = blockIdx.x * 64;
    float acc[4][4] = {};

    for (int k0 = 0; k0 < CC; k0 += 16) {
        {   // A: 64x16 tile, 4 floats/thread
            int r = tid >> 2, c = (tid & 3) * 4;
            float4 v = *(const float4*)(x + (long)(bm + r) * CC + k0 + c);
            As[r][c] = v.x; As[r][c+1] = v.y; As[r][c+2] = v.z; As[r][c+3] = v.w;
        }
        {   // B: 16x64 tile
            int r = tid >> 4, c = (tid & 15) * 4;
            float4 v = *(const float4*)(Wqkv + (long)(k0 + r) * C3 + bn + c);
            Bs[r][c] = v.x; Bs[r][c+1] = v.y; Bs[r][c+2] = v.z; Bs[r][c+3] = v.w;
        }
        __syncthreads();
        #pragma unroll
        for (int kk = 0; kk < 16; kk++) {
            float a[4], b[4];
            #pragma unroll
            for (int i = 0; i < 4; i++) a[i] = As[ty*4 + i][kk];
            #pragma unroll
            for (int j = 0; j < 4; j++) b[j] = Bs[kk][tx*4 + j];
            #pragma unroll
            for (int i = 0; i < 4; i++)
                #pragma unroll
                for (int j = 0; j < 4; j++)
                    acc[i][j] = fmaf(a[i], b[j], acc[i][j]);
        }
        __syncthreads();
    }

    // epilogue: RoPE on q,k (pairs are within the 4-wide micro-tile), scatter to [bh][t][d]
    #pragma unroll
    for (int i = 0; i < 4; i++) {
        int m = bm + ty*4 + i;
        int b = m / TT, t = m % TT;
        #pragma unroll
        for (int j = 0; j < 4; j += 2) {
            int n = bn + tx*4 + j;
            int sect = n / CC, rem = n % CC;
            int h = rem / HD, d = rem % HD;            // d even
            float v0 = acc[i][j], v1 = acc[i][j+1];
            long base = (((long)(b*HH + h)) * TT + t) * HD + d;
            if (sect == 2) {
                g_v[base] = v0; g_v[base + 1] = v1;
            } else {
                int jj = d >> 1;
                float c = g_cos[t*32 + jj], s = g_sin[t*32 + jj];
                float r0 = v0 * c - v1 * s;
                float r1 = v1 * c + v0 * s;
                float* dst = (sect == 0) ? g_q : g_k;
                dst[base] = r0; dst[base + 1] = r1;
            }
        }
    }
}

// ---------------- K2: scores = QK^T/8 - alibi, raw into attn region ----------------
__global__ __launch_bounds__(256) void k_scores(float* __restrict__ attn) {
    __shared__ float Qs[64][65];
    __shared__ float Ks[64][65];
    const int bh = blockIdx.z;
    const int h  = bh % HH;
    const int mq = blockIdx.y * 64, mk = blockIdx.x * 64;
    const float* qb = g_q + (long)bh * TT * HD;
    const float* kb = g_k + (long)bh * TT * HD;
    const int tid = threadIdx.x;

    #pragma unroll
    for (int r0 = 0; r0 < 64; r0 += 16) {
        int r = r0 + (tid >> 4), c = (tid & 15) * 4;
        float4 q4 = *(const float4*)(qb + (long)(mq + r) * HD + c);
        Qs[r][c] = q4.x; Qs[r][c+1] = q4.y; Qs[r][c+2] = q4.z; Qs[r][c+3] = q4.w;
        float4 k4 = *(const float4*)(kb + (long)(mk + r) * HD + c);
        Ks[r][c] = k4.x; Ks[r][c+1] = k4.y; Ks[r][c+2] = k4.z; Ks[r][c+3] = k4.w;
    }
    __syncthreads();

    const int tx = tid & 15, ty = tid >> 4;
    float acc[4][4] = {};
    #pragma unroll 8
    for (int kk = 0; kk < 64; kk++) {
        float a[4], b[4];
        #pragma unroll
        for (int i = 0; i < 4; i++) a[i] = Qs[ty*4 + i][kk];
        #pragma unroll
        for (int j = 0; j < 4; j++) b[j] = Ks[tx*4 + j][kk];
        #pragma unroll
        for (int i = 0; i < 4; i++)
            #pragma unroll
            for (int j = 0; j < 4; j++)
                acc[i][j] = fmaf(a[i], b[j], acc[i][j]);
    }

    const float slope = exp2f(-0.5f * (float)(h + 1));
    #pragma unroll
    for (int i = 0; i < 4; i++) {
        int tq = mq + ty*4 + i;
        #pragma unroll
        for (int j = 0; j < 4; j++) {
            int tk = mk + tx*4 + j;
            float s = acc[i][j] * 0.125f - slope * fabsf((float)(tq - tk));
            attn[((long)bh * TT + tq) * TT + tk] = s;
        }
    }
}

// ---------------- K3: row max + 1/sumexp ----------------
__global__ __launch_bounds__(256) void k_stats(const float* __restrict__ attn) {
    __shared__ float row[TT];
    __shared__ float red[256];
    const long r = blockIdx.x;
    const float* src = attn + r * TT;
    const int tid = threadIdx.x;

    float m = -INFINITY;
    for (int i = tid; i < TT; i += 256) { float v = src[i]; row[i] = v; m = fmaxf(m, v); }
    red[tid] = m; __syncthreads();
    for (int s = 128; s > 0; s >>= 1) { if (tid < s) red[tid] = fmaxf(red[tid], red[tid+s]); __syncthreads(); }
    m = red[0]; __syncthreads();

    float sum = 0.f;
    for (int i = tid; i < TT; i += 256) sum += expf(row[i] - m);
    red[tid] = sum; __syncthreads();
    for (int s = 128; s > 0; s >>= 1) { if (tid < s) red[tid] += red[tid+s]; __syncthreads(); }
    if (tid == 0) { g_rmax[r] = m; g_rinv[r] = 1.0f / red[0]; }
}

// ---------------- K4: P = softmax (written out as attn) fused with O = P @ V -------
__global__ __launch_bounds__(256) void k_pv(float* __restrict__ attn) {
    __shared__ float Ps[64][65];
    __shared__ float Vs[64][65];
    const int bh = blockIdx.y;
    const int mq = blockIdx.x * 64;
    float* arow = attn + ((long)bh * TT + mq) * TT;
    const float* vb = g_v + (long)bh * TT * HD;
    const int tid = threadIdx.x, tx = tid & 15, ty = tid >> 4;
    float acc[4][4] = {};

    for (int k0 = 0; k0 < TT; k0 += 64) {
        #pragma unroll
        for (int r0 = 0; r0 < 64; r0 += 16) {
            int r = r0 + (tid >> 4), c = (tid & 15) * 4;
            float4 s4 = *(const float4*)(arow + (long)r * TT + k0 + c);
            float rm = g_rmax[(long)bh * TT + mq + r];
            float ri = g_rinv[(long)bh * TT + mq + r];
            float4 p4;
            p4.x = expf(s4.x - rm) * ri;
            p4.y = expf(s4.y - rm) * ri;
            p4.z = expf(s4.z - rm) * ri;
            p4.w = expf(s4.w - rm) * ri;
            *(float4*)(arow + (long)r * TT + k0 + c) = p4;   // final attn output
            Ps[r][c] = p4.x; Ps[r][c+1] = p4.y; Ps[r][c+2] = p4.z; Ps[r][c+3] = p4.w;
            float4 v4 = *(const float4*)(vb + (long)(k0 + r) * HD + c);
            Vs[r][c] = v4.x; Vs[r][c+1] = v4.y; Vs[r][c+2] = v4.z; Vs[r][c+3] = v4.w;
        }
        __syncthreads();
        #pragma unroll 8
        for (int kk = 0; kk < 64; kk++) {
            float a[4], b[4];
            #pragma unroll
            for (int i = 0; i < 4; i++) a[i] = Ps[ty*4 + i][kk];
            #pragma unroll
            for (int j = 0; j < 4; j++) b[j] = Vs[kk][tx*4 + j];
            #pragma unroll
            for (int i = 0; i < 4; i++)
                #pragma unroll
                for (int j = 0; j < 4; j++)
                    acc[i][j] = fmaf(a[i], b[j], acc[i][j]);
        }
        __syncthreads();
    }

    #pragma unroll
    for (int i = 0; i < 4; i++)
        #pragma unroll
        for (int j = 0; j < 4; j++)
            g_o[((long)bh * TT + mq + ty*4 + i) * HD + tx*4 + j] = acc[i][j];
}

// ---------------- K5: out = O(reordered) @ W_out + b_out ----------------
__global__ __launch_bounds__(256) void k_outproj(const float* __restrict__ Wout,
                                                 const float* __restrict__ bout,
                                                 float* __restrict__ out) {
    __shared__ float As[64][17];
    __shared__ float Bs[16][68];
    const int tid = threadIdx.x;
    const int tx = tid & 15, ty = tid >> 4;
    const int bm = blockIdx.y * 64, bn = blockIdx.x * 64;
    float acc[4][4] = {};

    for (int k0 = 0; k0 < CC; k0 += 16) {
        {   // A: gather from g_o [bh][t][d]; k -> (h = k/64, d = k%64)
            int r = tid >> 2, c = (tid & 3) * 4;
            int m = bm + r, b = m / TT, t = m % TT;
            int k = k0 + c, h = k / HD, d = k % HD;
            float4 v = *(const float4*)(g_o + (((long)(b*HH + h)) * TT + t) * HD + d);
            As[r][c] = v.x; As[r][c+1] = v.y; As[r][c+2] = v.z; As[r][c+3] = v.w;
        }
        {
            int r = tid >> 4, c = (tid & 15) * 4;
            float4 v = *(const float4*)(Wout + (long)(k0 + r) * CC + bn + c);
            Bs[r][c] = v.x; Bs[r][c+1] = v.y; Bs[r][c+2] = v.z; Bs[r][c+3] = v.w;
        }
        __syncthreads();
        #pragma unroll
        for (int kk = 0; kk < 16; kk++) {
            float a[4], b[4];
            #pragma unroll
            for (int i = 0; i < 4; i++) a[i] = As[ty*4 + i][kk];
            #pragma unroll
            for (int j = 0; j < 4; j++) b[j] = Bs[kk][tx*4 + j];
            #pragma unroll
            for (int i = 0; i < 4; i++)
                #pragma unroll
                for (int j = 0; j < 4; j++)
                    acc[i][j] = fmaf(a[i], b[j], acc[i][j]);
        }
        __syncthreads();
    }

    #pragma unroll
    for (int i = 0; i < 4; i++) {
        int m = bm + ty*4 + i;
        #pragma unroll
        for (int j = 0; j < 4; j++) {
            int n = bn + tx*4 + j;
            out[(long)m * CC + n] = acc[i][j] + bout[n];
        }
    }
}

// ---------------- launch ----------------
extern "C" void kernel_launch(void* const* d_in, const int* in_sizes, int n_in,
                              void* d_out, int out_size) {
    const float* x    = (const float*)d_in[0];
    const float* Wqkv = (const float*)d_in[1];
    const float* Wout = (const float*)d_in[2];
    const float* bout = (const float*)d_in[3];
    float* out  = (float*)d_out;
    float* attn = out + (long)BB * TT * CC;   // output = (out, attn) concatenated

    k_rope_tab<<<256, 256>>>();
    k_qkv_rope<<<dim3(C3/64, (BB*TT)/64), 256>>>(x, Wqkv);
    k_scores  <<<dim3(TT/64, TT/64, NBH), 256>>>(attn);
    k_stats   <<<NBH*TT, 256>>>(attn);
    k_pv      <<<dim3(TT/64, NBH), 256>>>(attn);
    k_outproj <<<dim3(CC/64, (BB*TT)/64), 256>>>(Wout, bout, out);
}

// round 8
// speedup vs baseline: 1.5684x; 1.5684x over previous
#include <cuda_runtime.h>
#include <cuda_fp16.h>
#include <cstdint>
#include <math.h>

#define BB 2
#define TT 2048
#define CC 1024
#define HH 16
#define HD 64
#define NBH 32
#define C3 3072

// ---------------- device scratch (NEVER passed as kernel args) ----------------
__device__ float g_q[NBH*TT*HD];        // [bh][t][d]
__device__ float g_k[NBH*TT*HD];        // [bh][t][d]
__device__ float g_vt[NBH*HD*TT];       // [bh][d][t]
__device__ float g_o[NBH*TT*HD];        // [bh][t][d]
__device__ float g_rmax[NBH*TT];
__device__ float g_rinv[NBH*TT];
__device__ float g_cos[TT*32];
__device__ float g_sin[TT*32];
__device__ float g_wqkvT[C3*CC];        // [n][k]
__device__ float g_woutT[CC*CC];        // [n][k]

// ---------------- helpers ----------------
__device__ __forceinline__ void mma16816(float* d, const uint32_t* a, uint32_t b0, uint32_t b1) {
    asm volatile("mma.sync.aligned.m16n8k16.row.col.f32.f16.f16.f32 "
                 "{%0,%1,%2,%3}, {%4,%5,%6,%7}, {%8,%9}, {%0,%1,%2,%3};"
                 : "+f"(d[0]), "+f"(d[1]), "+f"(d[2]), "+f"(d[3])
                 : "r"(a[0]), "r"(a[1]), "r"(a[2]), "r"(a[3]), "r"(b0), "r"(b1));
}
// explicit A-fragment load per mma spec (spec-exact, verified):
//  a0={A[g][2tg..]}, a1={A[g+8][2tg..]}, a2={A[g][2tg+8..]}, a3={A[g+8][2tg+8..]}
__device__ __forceinline__ void lda(uint32_t* a, const __half* p, int str) {
    a[0] = *(const uint32_t*)(p);
    a[1] = *(const uint32_t*)(p + 8 * str);
    a[2] = *(const uint32_t*)(p + 8);
    a[3] = *(const uint32_t*)(p + 8 * str + 8);
}
__device__ __forceinline__ void splitst(__half* hi, __half* lo, int idx, float4 v) {
    __half h0 = __float2half_rn(v.x), h1 = __float2half_rn(v.y),
           h2 = __float2half_rn(v.z), h3 = __float2half_rn(v.w);
    __half l0 = __float2half_rn(v.x - __half2float(h0));
    __half l1 = __float2half_rn(v.y - __half2float(h1));
    __half l2 = __float2half_rn(v.z - __half2float(h2));
    __half l3 = __float2half_rn(v.w - __half2float(h3));
    __half2 H0 = __halves2half2(h0, h1), H1 = __halves2half2(h2, h3);
    __half2 L0 = __halves2half2(l0, l1), L1 = __halves2half2(l2, l3);
    uint2 HU, LU;
    HU.x = *reinterpret_cast<uint32_t*>(&H0); HU.y = *reinterpret_cast<uint32_t*>(&H1);
    LU.x = *reinterpret_cast<uint32_t*>(&L0); LU.y = *reinterpret_cast<uint32_t*>(&L1);
    *reinterpret_cast<uint2*>(hi + idx) = HU;
    *reinterpret_cast<uint2*>(lo + idx) = LU;
}

#define STR32 40
#define STR64 72

// ---------------- RoPE table ----------------
__global__ void k_rope_tab() {
    int idx = blockIdx.x * 256 + threadIdx.x;
    if (idx >= TT * 32) return;
    int t = idx / 32, j = idx % 32;
    int mi = (2 * j) % 32;
    float inv32 = (float)pow(10000.0, -(double)mi / 32.0);
    float th32 = (float)t * inv32;
    g_cos[idx] = (float)cos((double)th32);
    g_sin[idx] = (float)sin((double)th32);
}

// ---------------- transpose into device globals (dst resolved IN KERNEL) ----------------
__global__ void k_transpose(const float* __restrict__ src, int which, int K, int N) {
    __shared__ float tb[32][33];
    float* dst = which ? g_woutT : g_wqkvT;
    int n0 = blockIdx.x * 32, k0 = blockIdx.y * 32;
    for (int i = threadIdx.y; i < 32; i += 8)
        tb[i][threadIdx.x] = src[(size_t)(k0 + i) * N + n0 + threadIdx.x];
    __syncthreads();
    for (int i = threadIdx.y; i < 32; i += 8)
        dst[(size_t)(n0 + i) * K + k0 + threadIdx.x] = tb[threadIdx.x][i];
}

// ---------------- K1: QKV GEMM (HMMA 3-pass) + RoPE + scatter ----------------
__global__ __launch_bounds__(256) void k_qkv(const float* __restrict__ x) {
    extern __shared__ __half sm[];
    __half* Ah = sm;            // 128*40
    __half* Al = sm + 5120;
    __half* Bh = sm + 10240;
    __half* Bl = sm + 15360;
    const int tid = threadIdx.x, lane = tid & 31, wid = tid >> 5;
    const int wm = wid & 1, wn = wid >> 1, g = lane >> 2, tg = lane & 3;
    const int bn = blockIdx.x * 128, bm = blockIdx.y * 128;

    float acc[4][4][4] = {};
    const __half* aPH = Ah + (wm*64 + g) * STR32 + 2*tg;
    const __half* aPL = aPH + 5120;
    const __half* bpH = Bh + (wn*32 + g) * STR32 + 2*tg;
    const __half* bpL = bpH + 5120;

    for (int c = 0; c < 32; c++) {
        #pragma unroll
        for (int i = 0; i < 4; i++) {
            int f = tid + i*256, row = f >> 3, c4 = f & 7;
            float4 va = *(const float4*)(x + (size_t)(bm+row)*CC + c*32 + c4*4);
            splitst(Ah, Al, row*STR32 + c4*4, va);
            float4 vb = *(const float4*)(g_wqkvT + (size_t)(bn+row)*CC + c*32 + c4*4);
            splitst(Bh, Bl, row*STR32 + c4*4, vb);
        }
        __syncthreads();
        #pragma unroll
        for (int ks = 0; ks < 2; ks++) {
            uint32_t ah[4][4], al[4][4];
            #pragma unroll
            for (int mf = 0; mf < 4; mf++) {
                int off = mf*16*STR32 + ks*16;
                lda(ah[mf], aPH + off, STR32);
                lda(al[mf], aPL + off, STR32);
            }
            #pragma unroll
            for (int nf = 0; nf < 4; nf++) {
                const __half* ph = bpH + nf*8*STR32 + ks*16;
                const __half* pl = bpL + nf*8*STR32 + ks*16;
                uint32_t bh0 = *(const uint32_t*)ph, bh1 = *(const uint32_t*)(ph + 8);
                uint32_t bl0 = *(const uint32_t*)pl, bl1 = *(const uint32_t*)(pl + 8);
                #pragma unroll
                for (int mf = 0; mf < 4; mf++) {
                    mma16816(acc[mf][nf], ah[mf], bh0, bh1);
                    mma16816(acc[mf][nf], al[mf], bh0, bh1);
                    mma16816(acc[mf][nf], ah[mf], bl0, bl1);
                }
            }
        }
        __syncthreads();
    }
    #pragma unroll
    for (int mf = 0; mf < 4; mf++) {
        #pragma unroll
        for (int half = 0; half < 2; half++) {
            int m = bm + wm*64 + mf*16 + g + half*8;
            int b = m >> 11, t = m & 2047;
            #pragma unroll
            for (int nf = 0; nf < 4; nf++) {
                int n = bn + wn*32 + nf*8 + 2*tg;
                float v0 = acc[mf][nf][half*2 + 0], v1 = acc[mf][nf][half*2 + 1];
                int sect = n >> 10, rem = n & 1023, hh = rem >> 6, d = rem & 63;
                if (sect == 2) {
                    size_t base = ((size_t)(b*HH + hh) * HD + d) * TT + t;
                    g_vt[base] = v0; g_vt[base + TT] = v1;
                } else {
                    int j2 = d >> 1;
                    float cs = g_cos[t*32 + j2], sn = g_sin[t*32 + j2];
                    float r0 = v0*cs - v1*sn, r1 = v1*cs + v0*sn;
                    float* dst = sect ? g_k : g_q;
                    *(float2*)(dst + ((size_t)(b*HH + hh)*TT + t)*HD + d) = make_float2(r0, r1);
                }
            }
        }
    }
}

// ---------------- K2: scores = QK^T/8 - alibi + fused flash row stats ----------------
__global__ __launch_bounds__(256) void k_scores(float* __restrict__ attn) {
    extern __shared__ __half sm[];
    __half* Qh = sm;                // 128*72
    __half* Ql = sm + 9216;
    __half* Kh = sm + 18432;
    __half* Kl = sm + 27648;
    float* srd_m = (float*)(sm + 36864);   // [4][128]
    float* srd_s = srd_m + 512;
    const int tid = threadIdx.x, lane = tid & 31, wid = tid >> 5;
    const int wm = wid & 1, wn = wid >> 1, g = lane >> 2, tg = lane & 3;
    const int bh = blockIdx.y, h = bh & 15, q0 = blockIdx.x * 128;
    const float* qb = g_q + (size_t)bh * TT * HD;
    const float* kb = g_k + (size_t)bh * TT * HD;

    #pragma unroll
    for (int i = 0; i < 8; i++) {
        int f = tid + i*256, row = f >> 4, c4 = f & 15;
        float4 v = *(const float4*)(qb + (size_t)(q0+row)*HD + c4*4);
        splitst(Qh, Ql, row*STR64 + c4*4, v);
    }
    const __half* aPH = Qh + (wm*64 + g) * STR64 + 2*tg;
    const __half* aPL = aPH + 9216;
    const __half* bpH = Kh + (wn*32 + g) * STR64 + 2*tg;
    const __half* bpL = bpH + 9216;
    const float slope = exp2f(-0.5f * (float)(h + 1));
    float rm[8], rs[8];
    #pragma unroll
    for (int i = 0; i < 8; i++) { rm[i] = -INFINITY; rs[i] = 0.f; }

    for (int nt = 0; nt < 16; nt++) {
        #pragma unroll
        for (int i = 0; i < 8; i++) {
            int f = tid + i*256, row = f >> 4, c4 = f & 15;
            float4 v = *(const float4*)(kb + (size_t)(nt*128 + row)*HD + c4*4);
            splitst(Kh, Kl, row*STR64 + c4*4, v);
        }
        __syncthreads();
        float acc[4][4][4] = {};
        #pragma unroll
        for (int ks = 0; ks < 4; ks++) {
            uint32_t ah[4][4], al[4][4];
            #pragma unroll
            for (int mf = 0; mf < 4; mf++) {
                int off = mf*16*STR64 + ks*16;
                lda(ah[mf], aPH + off, STR64);
                lda(al[mf], aPL + off, STR64);
            }
            #pragma unroll
            for (int nf = 0; nf < 4; nf++) {
                const __half* ph = bpH + nf*8*STR64 + ks*16;
                const __half* pl = bpL + nf*8*STR64 + ks*16;
                uint32_t bh0 = *(const uint32_t*)ph, bh1 = *(const uint32_t*)(ph + 8);
                uint32_t bl0 = *(const uint32_t*)pl, bl1 = *(const uint32_t*)(pl + 8);
                #pragma unroll
                for (int mf = 0; mf < 4; mf++) {
                    mma16816(acc[mf][nf], ah[mf], bh0, bh1);
                    mma16816(acc[mf][nf], al[mf], bh0, bh1);
                    mma16816(acc[mf][nf], ah[mf], bl0, bl1);
                }
            }
        }
        #pragma unroll
        for (int mf = 0; mf < 4; mf++) {
            #pragma unroll
            for (int half = 0; half < 2; half++) {
                int r = wm*64 + mf*16 + g + half*8;
                int q = q0 + r;
                float vv[8];
                float tmax = -INFINITY;
                #pragma unroll
                for (int nf = 0; nf < 4; nf++) {
                    int col = nt*128 + wn*32 + nf*8 + 2*tg;
                    float v0 = acc[mf][nf][half*2+0] * 0.125f - slope * fabsf((float)(q - col));
                    float v1 = acc[mf][nf][half*2+1] * 0.125f - slope * fabsf((float)(q - col - 1));
                    vv[nf*2] = v0; vv[nf*2+1] = v1;
                    *(float2*)(attn + ((size_t)bh*TT + q)*TT + col) = make_float2(v0, v1);
                    tmax = fmaxf(tmax, fmaxf(v0, v1));
                }
                int ri = mf*2 + half;
                float nm = fmaxf(rm[ri], tmax);
                float s = 0.f;
                #pragma unroll
                for (int j = 0; j < 8; j++) s += expf(vv[j] - nm);
                rs[ri] = rs[ri] * expf(rm[ri] - nm) + s;
                rm[ri] = nm;
            }
        }
        __syncthreads();
    }
    // reduce stats across tg lanes (xor 1,2), then across wn via smem
    #pragma unroll
    for (int i = 0; i < 8; i++) {
        #pragma unroll
        for (int dd = 1; dd < 4; dd <<= 1) {
            float om = __shfl_xor_sync(0xffffffffu, rm[i], dd);
            float os = __shfl_xor_sync(0xffffffffu, rs[i], dd);
            float nm = fmaxf(rm[i], om);
            rs[i] = rs[i] * expf(rm[i] - nm) + os * expf(om - nm);
            rm[i] = nm;
        }
    }
    if (tg == 0) {
        #pragma unroll
        for (int mf = 0; mf < 4; mf++)
            #pragma unroll
            for (int half = 0; half < 2; half++) {
                int r = wm*64 + mf*16 + g + half*8;
                srd_m[wn*128 + r] = rm[mf*2 + half];
                srd_s[wn*128 + r] = rs[mf*2 + half];
            }
    }
    __syncthreads();
    if (tid < 128) {
        float m = srd_m[tid], s = srd_s[tid];
        #pragma unroll
        for (int w = 1; w < 4; w++) {
            float om = srd_m[w*128 + tid], os = srd_s[w*128 + tid];
            float nm = fmaxf(m, om);
            s = s * expf(m - nm) + os * expf(om - nm);
            m = nm;
        }
        g_rmax[(size_t)bh*TT + q0 + tid] = m;
        g_rinv[(size_t)bh*TT + q0 + tid] = 1.0f / s;
    }
}

// ---------------- K3: normalize P (final attn) + O = P @ V ----------------
__global__ __launch_bounds__(256) void k_pv(float* __restrict__ attn) {
    extern __shared__ __half sm[];
    __half* Ph = sm;              // 256*40
    __half* Pl = sm + 10240;
    __half* Vh = sm + 20480;      // 64*40
    __half* Vl = sm + 23040;
    float* srm = (float*)(sm + 25600);   // 256
    float* sri = srm + 256;
    const int tid = threadIdx.x, lane = tid & 31, wid = tid >> 5;
    const int wm = wid & 3, wn = wid >> 2, g = lane >> 2, tg = lane & 3;
    const int bh = blockIdx.y, q0 = blockIdx.x * 256;
    srm[tid] = g_rmax[(size_t)bh*TT + q0 + tid];
    sri[tid] = g_rinv[(size_t)bh*TT + q0 + tid];
    __syncthreads();
    float acc[4][4][4] = {};
    const __half* aPH = Ph + (wm*64 + g) * STR32 + 2*tg;
    const __half* aPL = aPH + 10240;
    const __half* bpH = Vh + (wn*32 + g) * STR32 + 2*tg;
    const __half* bpL = bpH + 2560;
    const float* vtb = g_vt + (size_t)bh * HD * TT;

    for (int c = 0; c < 64; c++) {
        #pragma unroll
        for (int i = 0; i < 8; i++) {
            int f = tid + i*256, row = f >> 3, c4 = f & 7;
            size_t off = ((size_t)bh*TT + q0 + row)*TT + c*32 + c4*4;
            float4 v = *(const float4*)(attn + off);
            float m = srm[row], iv = sri[row];
            float4 p;
            p.x = expf(v.x - m) * iv;
            p.y = expf(v.y - m) * iv;
            p.z = expf(v.z - m) * iv;
            p.w = expf(v.w - m) * iv;
            *(float4*)(attn + off) = p;               // final attn output
            splitst(Ph, Pl, row*STR32 + c4*4, p);
        }
        #pragma unroll
        for (int i = 0; i < 2; i++) {
            int f = tid + i*256, row = f >> 3, c4 = f & 7;   // rows 0..63 (= d)
            float4 v = *(const float4*)(vtb + (size_t)row*TT + c*32 + c4*4);
            splitst(Vh, Vl, row*STR32 + c4*4, v);
        }
        __syncthreads();
        #pragma unroll
        for (int ks = 0; ks < 2; ks++) {
            uint32_t ah[4][4], al[4][4];
            #pragma unroll
            for (int mf = 0; mf < 4; mf++) {
                int off = mf*16*STR32 + ks*16;
                lda(ah[mf], aPH + off, STR32);
                lda(al[mf], aPL + off, STR32);
            }
            #pragma unroll
            for (int nf = 0; nf < 4; nf++) {
                const __half* ph = bpH + nf*8*STR32 + ks*16;
                const __half* pl = bpL + nf*8*STR32 + ks*16;
                uint32_t bh0 = *(const uint32_t*)ph, bh1 = *(const uint32_t*)(ph + 8);
                uint32_t bl0 = *(const uint32_t*)pl, bl1 = *(const uint32_t*)(pl + 8);
                #pragma unroll
                for (int mf = 0; mf < 4; mf++) {
                    mma16816(acc[mf][nf], ah[mf], bh0, bh1);
                    mma16816(acc[mf][nf], al[mf], bh0, bh1);
                    mma16816(acc[mf][nf], ah[mf], bl0, bl1);
                }
            }
        }
        __syncthreads();
    }
    #pragma unroll
    for (int mf = 0; mf < 4; mf++) {
        int r = q0 + wm*64 + mf*16 + g;
        #pragma unroll
        for (int nf = 0; nf < 4; nf++) {
            int ccol = wn*32 + nf*8 + 2*tg;
            *(float2*)(g_o + ((size_t)bh*TT + r)*HD + ccol)     = make_float2(acc[mf][nf][0], acc[mf][nf][1]);
            *(float2*)(g_o + ((size_t)bh*TT + r + 8)*HD + ccol) = make_float2(acc[mf][nf][2], acc[mf][nf][3]);
        }
    }
}

// ---------------- K4: out = O @ W_out + b ----------------
__global__ __launch_bounds__(256) void k_outproj(const float* __restrict__ bout,
                                                 float* __restrict__ out) {
    extern __shared__ __half sm[];
    __half* Ah = sm;
    __half* Al = sm + 5120;
    __half* Bh = sm + 10240;
    __half* Bl = sm + 15360;
    const int tid = threadIdx.x, lane = tid & 31, wid = tid >> 5;
    const int wm = wid & 1, wn = wid >> 1, g = lane >> 2, tg = lane & 3;
    const int bn = blockIdx.x * 128, bm = blockIdx.y * 128;

    float acc[4][4][4] = {};
    const __half* aPH = Ah + (wm*64 + g) * STR32 + 2*tg;
    const __half* aPL = aPH + 5120;
    const __half* bpH = Bh + (wn*32 + g) * STR32 + 2*tg;
    const __half* bpL = bpH + 5120;

    for (int c = 0; c < 32; c++) {
        #pragma unroll
        for (int i = 0; i < 4; i++) {
            int f = tid + i*256, row = f >> 3, c4 = f & 7;
            int m = bm + row, b = m >> 11, t = m & 2047;
            int kk = c*32 + c4*4, hh = kk >> 6, dd = kk & 63;
            float4 va = *(const float4*)(g_o + ((size_t)(b*HH + hh)*TT + t)*HD + dd);
            splitst(Ah, Al, row*STR32 + c4*4, va);
            float4 vb = *(const float4*)(g_woutT + (size_t)(bn+row)*CC + c*32 + c4*4);
            splitst(Bh, Bl, row*STR32 + c4*4, vb);
        }
        __syncthreads();
        #pragma unroll
        for (int ks = 0; ks < 2; ks++) {
            uint32_t ah[4][4], al[4][4];
            #pragma unroll
            for (int mf = 0; mf < 4; mf++) {
                int off = mf*16*STR32 + ks*16;
                lda(ah[mf], aPH + off, STR32);
                lda(al[mf], aPL + off, STR32);
            }
            #pragma unroll
            for (int nf = 0; nf < 4; nf++) {
                const __half* ph = bpH + nf*8*STR32 + ks*16;
                const __half* pl = bpL + nf*8*STR32 + ks*16;
                uint32_t bh0 = *(const uint32_t*)ph, bh1 = *(const uint32_t*)(ph + 8);
                uint32_t bl0 = *(const uint32_t*)pl, bl1 = *(const uint32_t*)(pl + 8);
                #pragma unroll
                for (int mf = 0; mf < 4; mf++) {
                    mma16816(acc[mf][nf], ah[mf], bh0, bh1);
                    mma16816(acc[mf][nf], al[mf], bh0, bh1);
                    mma16816(acc[mf][nf], ah[mf], bl0, bl1);
                }
            }
        }
        __syncthreads();
    }
    #pragma unroll
    for (int mf = 0; mf < 4; mf++) {
        #pragma unroll
        for (int half = 0; half < 2; half++) {
            int m = bm + wm*64 + mf*16 + g + half*8;
            #pragma unroll
            for (int nf = 0; nf < 4; nf++) {
                int n = bn + wn*32 + nf*8 + 2*tg;
                float2 o = make_float2(acc[mf][nf][half*2+0] + bout[n],
                                       acc[mf][nf][half*2+1] + bout[n+1]);
                *(float2*)(out + (size_t)m*CC + n) = o;
            }
        }
    }
}

// ---------------- launch ----------------
extern "C" void kernel_launch(void* const* d_in, const int* in_sizes, int n_in,
                              void* d_out, int out_size) {
    const float* x    = (const float*)d_in[0];
    const float* Wqkv = (const float*)d_in[1];
    const float* Wout = (const float*)d_in[2];
    const float* bout = (const float*)d_in[3];
    float* out  = (float*)d_out;
    float* attn = out + (size_t)BB * TT * CC;

    cudaFuncSetAttribute(k_scores, cudaFuncAttributeMaxDynamicSharedMemorySize, 77824);
    cudaFuncSetAttribute(k_pv,     cudaFuncAttributeMaxDynamicSharedMemorySize, 53248);

    k_rope_tab<<<256, 256>>>();
    k_transpose<<<dim3(C3 / 32, CC / 32), dim3(32, 8)>>>(Wqkv, 0, CC, C3);
    k_transpose<<<dim3(CC / 32, CC / 32), dim3(32, 8)>>>(Wout, 1, CC, CC);
    k_qkv    <<<dim3(C3 / 128, (BB * TT) / 128), 256, 40960>>>(x);
    k_scores <<<dim3(TT / 128, NBH), 256, 77824>>>(attn);
    k_pv     <<<dim3(TT / 256, NBH), 256, 53248>>>(attn);
    k_outproj<<<dim3(CC / 128, (BB * TT) / 128), 256, 40960>>>(bout, out);
}

// round 9
// speedup vs baseline: 1.9259x; 1.2279x over previous
#include <cuda_runtime.h>
#include <cuda_fp16.h>
#include <cstdint>
#include <math.h>

#define BB 2
#define TT 2048
#define CC 1024
#define HH 16
#define HD 64
#define NBH 32
#define C3 3072

// ---------------- device scratch (NEVER passed as kernel args) ----------------
__device__ float g_q[NBH*TT*HD];        // [bh][t][d]
__device__ float g_k[NBH*TT*HD];        // [bh][t][d]
__device__ float g_vt[NBH*HD*TT];       // [bh][d][t]
__device__ float g_o[NBH*TT*HD];        // [bh][t][d]
__device__ float g_rmax[NBH*TT];
__device__ float g_rinv[NBH*TT];
__device__ float g_cos[TT*32];
__device__ float g_sin[TT*32];
__device__ float g_wqkvT[C3*CC];        // [n][k]
__device__ float g_woutT[CC*CC];        // [n][k]

// ---------------- helpers ----------------
__device__ __forceinline__ void mma16816(float* d, const uint32_t* a, uint32_t b0, uint32_t b1) {
    asm volatile("mma.sync.aligned.m16n8k16.row.col.f32.f16.f16.f32 "
                 "{%0,%1,%2,%3}, {%4,%5,%6,%7}, {%8,%9}, {%0,%1,%2,%3};"
                 : "+f"(d[0]), "+f"(d[1]), "+f"(d[2]), "+f"(d[3])
                 : "r"(a[0]), "r"(a[1]), "r"(a[2]), "r"(a[3]), "r"(b0), "r"(b1));
}
// explicit A-fragment load per mma spec:
//  a0={A[g][2tg..]}, a1={A[g+8][2tg..]}, a2={A[g][2tg+8..]}, a3={A[g+8][2tg+8..]}
__device__ __forceinline__ void lda(uint32_t* a, const __half* p, int str) {
    a[0] = *(const uint32_t*)(p);
    a[1] = *(const uint32_t*)(p + 8 * str);
    a[2] = *(const uint32_t*)(p + 8);
    a[3] = *(const uint32_t*)(p + 8 * str + 8);
}
// hi/lo split store (A operands)
__device__ __forceinline__ void splitst(__half* hi, __half* lo, int idx, float4 v) {
    __half h0 = __float2half_rn(v.x), h1 = __float2half_rn(v.y),
           h2 = __float2half_rn(v.z), h3 = __float2half_rn(v.w);
    __half l0 = __float2half_rn(v.x - __half2float(h0));
    __half l1 = __float2half_rn(v.y - __half2float(h1));
    __half l2 = __float2half_rn(v.z - __half2float(h2));
    __half l3 = __float2half_rn(v.w - __half2float(h3));
    __half2 H0 = __halves2half2(h0, h1), H1 = __halves2half2(h2, h3);
    __half2 L0 = __halves2half2(l0, l1), L1 = __halves2half2(l2, l3);
    uint2 HU, LU;
    HU.x = *reinterpret_cast<uint32_t*>(&H0); HU.y = *reinterpret_cast<uint32_t*>(&H1);
    LU.x = *reinterpret_cast<uint32_t*>(&L0); LU.y = *reinterpret_cast<uint32_t*>(&L1);
    *reinterpret_cast<uint2*>(hi + idx) = HU;
    *reinterpret_cast<uint2*>(lo + idx) = LU;
}
// hi-only store (B operands — 2-pass compensation)
__device__ __forceinline__ void splitst_h(__half* hi, int idx, float4 v) {
    __half2 H0 = __halves2half2(__float2half_rn(v.x), __float2half_rn(v.y));
    __half2 H1 = __halves2half2(__float2half_rn(v.z), __float2half_rn(v.w));
    uint2 HU;
    HU.x = *reinterpret_cast<uint32_t*>(&H0); HU.y = *reinterpret_cast<uint32_t*>(&H1);
    *reinterpret_cast<uint2*>(hi + idx) = HU;
}

#define STR32 40
#define STR64 72

// ---------------- RoPE table ----------------
__global__ void k_rope_tab() {
    int idx = blockIdx.x * 256 + threadIdx.x;
    if (idx >= TT * 32) return;
    int t = idx / 32, j = idx % 32;
    int mi = (2 * j) % 32;
    float inv32 = (float)pow(10000.0, -(double)mi / 32.0);
    float th32 = (float)t * inv32;
    g_cos[idx] = (float)cos((double)th32);
    g_sin[idx] = (float)sin((double)th32);
}

// ---------------- transpose into device globals (dst resolved IN KERNEL) ----------------
__global__ void k_transpose(const float* __restrict__ src, int which, int K, int N) {
    __shared__ float tb[32][33];
    float* dst = which ? g_woutT : g_wqkvT;
    int n0 = blockIdx.x * 32, k0 = blockIdx.y * 32;
    for (int i = threadIdx.y; i < 32; i += 8)
        tb[i][threadIdx.x] = src[(size_t)(k0 + i) * N + n0 + threadIdx.x];
    __syncthreads();
    for (int i = threadIdx.y; i < 32; i += 8)
        dst[(size_t)(n0 + i) * K + k0 + threadIdx.x] = tb[threadIdx.x][i];
}

// ---------------- K1: QKV GEMM (HMMA 2-pass) + RoPE + scatter ----------------
__global__ __launch_bounds__(256, 2) void k_qkv(const float* __restrict__ x) {
    extern __shared__ __half sm[];
    __half* Ah = sm;            // 128*40
    __half* Al = sm + 5120;
    __half* Bh = sm + 10240;
    const int tid = threadIdx.x, lane = tid & 31, wid = tid >> 5;
    const int wm = wid & 1, wn = wid >> 1, g = lane >> 2, tg = lane & 3;
    const int bn = blockIdx.x * 128, bm = blockIdx.y * 128;

    float acc[4][4][4] = {};
    const __half* aPH = Ah + (wm*64 + g) * STR32 + 2*tg;
    const __half* aPL = aPH + 5120;
    const __half* bpH = Bh + (wn*32 + g) * STR32 + 2*tg;

    for (int c = 0; c < 32; c++) {
        #pragma unroll
        for (int i = 0; i < 4; i++) {
            int f = tid + i*256, row = f >> 3, c4 = f & 7;
            float4 va = *(const float4*)(x + (size_t)(bm+row)*CC + c*32 + c4*4);
            splitst(Ah, Al, row*STR32 + c4*4, va);
            float4 vb = *(const float4*)(g_wqkvT + (size_t)(bn+row)*CC + c*32 + c4*4);
            splitst_h(Bh, row*STR32 + c4*4, vb);
        }
        __syncthreads();
        #pragma unroll
        for (int ks = 0; ks < 2; ks++) {
            uint32_t ah[4][4], al[4][4];
            #pragma unroll
            for (int mf = 0; mf < 4; mf++) {
                int off = mf*16*STR32 + ks*16;
                lda(ah[mf], aPH + off, STR32);
                lda(al[mf], aPL + off, STR32);
            }
            #pragma unroll
            for (int nf = 0; nf < 4; nf++) {
                const __half* ph = bpH + nf*8*STR32 + ks*16;
                uint32_t bh0 = *(const uint32_t*)ph, bh1 = *(const uint32_t*)(ph + 8);
                #pragma unroll
                for (int mf = 0; mf < 4; mf++) {
                    mma16816(acc[mf][nf], ah[mf], bh0, bh1);
                    mma16816(acc[mf][nf], al[mf], bh0, bh1);
                }
            }
        }
        __syncthreads();
    }
    #pragma unroll
    for (int mf = 0; mf < 4; mf++) {
        #pragma unroll
        for (int half = 0; half < 2; half++) {
            int m = bm + wm*64 + mf*16 + g + half*8;
            int b = m >> 11, t = m & 2047;
            #pragma unroll
            for (int nf = 0; nf < 4; nf++) {
                int n = bn + wn*32 + nf*8 + 2*tg;
                float v0 = acc[mf][nf][half*2 + 0], v1 = acc[mf][nf][half*2 + 1];
                int sect = n >> 10, rem = n & 1023, hh = rem >> 6, d = rem & 63;
                if (sect == 2) {
                    size_t base = ((size_t)(b*HH + hh) * HD + d) * TT + t;
                    g_vt[base] = v0; g_vt[base + TT] = v1;
                } else {
                    int j2 = d >> 1;
                    float cs = g_cos[t*32 + j2], sn = g_sin[t*32 + j2];
                    float r0 = v0*cs - v1*sn, r1 = v1*cs + v0*sn;
                    float* dst = sect ? g_k : g_q;
                    *(float2*)(dst + ((size_t)(b*HH + hh)*TT + t)*HD + d) = make_float2(r0, r1);
                }
            }
        }
    }
}

// ---------------- K2: scores = QK^T/8 - alibi + fused flash row stats ----------------
__global__ __launch_bounds__(256, 2) void k_scores(float* __restrict__ attn) {
    extern __shared__ __half sm[];
    __half* Qh = sm;                // 128*72
    __half* Ql = sm + 9216;
    __half* Kh = sm + 18432;
    float* srd_m = (float*)(sm + 27648);   // [4][128]
    float* srd_s = srd_m + 512;
    const int tid = threadIdx.x, lane = tid & 31, wid = tid >> 5;
    const int wm = wid & 1, wn = wid >> 1, g = lane >> 2, tg = lane & 3;
    const int bh = blockIdx.y, h = bh & 15, q0 = blockIdx.x * 128;
    const float* qb = g_q + (size_t)bh * TT * HD;
    const float* kb = g_k + (size_t)bh * TT * HD;

    #pragma unroll
    for (int i = 0; i < 8; i++) {
        int f = tid + i*256, row = f >> 4, c4 = f & 15;
        float4 v = *(const float4*)(qb + (size_t)(q0+row)*HD + c4*4);
        splitst(Qh, Ql, row*STR64 + c4*4, v);
    }
    const __half* aPH = Qh + (wm*64 + g) * STR64 + 2*tg;
    const __half* aPL = aPH + 9216;
    const __half* bpH = Kh + (wn*32 + g) * STR64 + 2*tg;
    const float slope = exp2f(-0.5f * (float)(h + 1));
    float rm[8], rs[8];
    #pragma unroll
    for (int i = 0; i < 8; i++) { rm[i] = -INFINITY; rs[i] = 0.f; }

    for (int nt = 0; nt < 16; nt++) {
        #pragma unroll
        for (int i = 0; i < 8; i++) {
            int f = tid + i*256, row = f >> 4, c4 = f & 15;
            float4 v = *(const float4*)(kb + (size_t)(nt*128 + row)*HD + c4*4);
            splitst_h(Kh, row*STR64 + c4*4, v);
        }
        __syncthreads();
        float acc[4][4][4] = {};
        #pragma unroll
        for (int ks = 0; ks < 4; ks++) {
            uint32_t ah[4][4], al[4][4];
            #pragma unroll
            for (int mf = 0; mf < 4; mf++) {
                int off = mf*16*STR64 + ks*16;
                lda(ah[mf], aPH + off, STR64);
                lda(al[mf], aPL + off, STR64);
            }
            #pragma unroll
            for (int nf = 0; nf < 4; nf++) {
                const __half* ph = bpH + nf*8*STR64 + ks*16;
                uint32_t bh0 = *(const uint32_t*)ph, bh1 = *(const uint32_t*)(ph + 8);
                #pragma unroll
                for (int mf = 0; mf < 4; mf++) {
                    mma16816(acc[mf][nf], ah[mf], bh0, bh1);
                    mma16816(acc[mf][nf], al[mf], bh0, bh1);
                }
            }
        }
        #pragma unroll
        for (int mf = 0; mf < 4; mf++) {
            #pragma unroll
            for (int half = 0; half < 2; half++) {
                int r = wm*64 + mf*16 + g + half*8;
                int q = q0 + r;
                float vv[8];
                float tmax = -INFINITY;
                #pragma unroll
                for (int nf = 0; nf < 4; nf++) {
                    int col = nt*128 + wn*32 + nf*8 + 2*tg;
                    float v0 = acc[mf][nf][half*2+0] * 0.125f - slope * fabsf((float)(q - col));
                    float v1 = acc[mf][nf][half*2+1] * 0.125f - slope * fabsf((float)(q - col - 1));
                    vv[nf*2] = v0; vv[nf*2+1] = v1;
                    *(float2*)(attn + ((size_t)bh*TT + q)*TT + col) = make_float2(v0, v1);
                    tmax = fmaxf(tmax, fmaxf(v0, v1));
                }
                int ri = mf*2 + half;
                float nm = fmaxf(rm[ri], tmax);
                float s = 0.f;
                #pragma unroll
                for (int j = 0; j < 8; j++) s += expf(vv[j] - nm);
                rs[ri] = rs[ri] * expf(rm[ri] - nm) + s;
                rm[ri] = nm;
            }
        }
        __syncthreads();
    }
    #pragma unroll
    for (int i = 0; i < 8; i++) {
        #pragma unroll
        for (int dd = 1; dd < 4; dd <<= 1) {
            float om = __shfl_xor_sync(0xffffffffu, rm[i], dd);
            float os = __shfl_xor_sync(0xffffffffu, rs[i], dd);
            float nm = fmaxf(rm[i], om);
            rs[i] = rs[i] * expf(rm[i] - nm) + os * expf(om - nm);
            rm[i] = nm;
        }
    }
    if (tg == 0) {
        #pragma unroll
        for (int mf = 0; mf < 4; mf++)
            #pragma unroll
            for (int half = 0; half < 2; half++) {
                int r = wm*64 + mf*16 + g + half*8;
                srd_m[wn*128 + r] = rm[mf*2 + half];
                srd_s[wn*128 + r] = rs[mf*2 + half];
            }
    }
    __syncthreads();
    if (tid < 128) {
        float m = srd_m[tid], s = srd_s[tid];
        #pragma unroll
        for (int w = 1; w < 4; w++) {
            float om = srd_m[w*128 + tid], os = srd_s[w*128 + tid];
            float nm = fmaxf(m, om);
            s = s * expf(m - nm) + os * expf(om - nm);
            m = nm;
        }
        g_rmax[(size_t)bh*TT + q0 + tid] = m;
        g_rinv[(size_t)bh*TT + q0 + tid] = 1.0f / s;
    }
}

// ---------------- K3: normalize P (final attn) + O = P @ V ----------------
__global__ __launch_bounds__(256, 2) void k_pv(float* __restrict__ attn) {
    extern __shared__ __half sm[];
    __half* Ph = sm;              // 256*40
    __half* Pl = sm + 10240;
    __half* Vh = sm + 20480;      // 64*40
    float* srm = (float*)(sm + 23040);   // 256
    float* sri = srm + 256;
    const int tid = threadIdx.x, lane = tid & 31, wid = tid >> 5;
    const int wm = wid & 3, wn = wid >> 2, g = lane >> 2, tg = lane & 3;
    const int bh = blockIdx.y, q0 = blockIdx.x * 256;
    srm[tid] = g_rmax[(size_t)bh*TT + q0 + tid];
    sri[tid] = g_rinv[(size_t)bh*TT + q0 + tid];
    __syncthreads();
    float acc[4][4][4] = {};
    const __half* aPH = Ph + (wm*64 + g) * STR32 + 2*tg;
    const __half* aPL = aPH + 10240;
    const __half* bpH = Vh + (wn*32 + g) * STR32 + 2*tg;
    const float* vtb = g_vt + (size_t)bh * HD * TT;

    for (int c = 0; c < 64; c++) {
        #pragma unroll
        for (int i = 0; i < 8; i++) {
            int f = tid + i*256, row = f >> 3, c4 = f & 7;
            size_t off = ((size_t)bh*TT + q0 + row)*TT + c*32 + c4*4;
            float4 v = *(const float4*)(attn + off);
            float m = srm[row], iv = sri[row];
            float4 p;
            p.x = expf(v.x - m) * iv;
            p.y = expf(v.y - m) * iv;
            p.z = expf(v.z - m) * iv;
            p.w = expf(v.w - m) * iv;
            *(float4*)(attn + off) = p;               // final attn output
            splitst(Ph, Pl, row*STR32 + c4*4, p);
        }
        #pragma unroll
        for (int i = 0; i < 2; i++) {
            int f = tid + i*256, row = f >> 3, c4 = f & 7;   // rows 0..63 (= d)
            float4 v = *(const float4*)(vtb + (size_t)row*TT + c*32 + c4*4);
            splitst_h(Vh, row*STR32 + c4*4, v);
        }
        __syncthreads();
        #pragma unroll
        for (int ks = 0; ks < 2; ks++) {
            uint32_t ah[4][4], al[4][4];
            #pragma unroll
            for (int mf = 0; mf < 4; mf++) {
                int off = mf*16*STR32 + ks*16;
                lda(ah[mf], aPH + off, STR32);
                lda(al[mf], aPL + off, STR32);
            }
            #pragma unroll
            for (int nf = 0; nf < 4; nf++) {
                const __half* ph = bpH + nf*8*STR32 + ks*16;
                uint32_t bh0 = *(const uint32_t*)ph, bh1 = *(const uint32_t*)(ph + 8);
                #pragma unroll
                for (int mf = 0; mf < 4; mf++) {
                    mma16816(acc[mf][nf], ah[mf], bh0, bh1);
                    mma16816(acc[mf][nf], al[mf], bh0, bh1);
                }
            }
        }
        __syncthreads();
    }
    #pragma unroll
    for (int mf = 0; mf < 4; mf++) {
        int r = q0 + wm*64 + mf*16 + g;
        #pragma unroll
        for (int nf = 0; nf < 4; nf++) {
            int ccol = wn*32 + nf*8 + 2*tg;
            *(float2*)(g_o + ((size_t)bh*TT + r)*HD + ccol)     = make_float2(acc[mf][nf][0], acc[mf][nf][1]);
            *(float2*)(g_o + ((size_t)bh*TT + r + 8)*HD + ccol) = make_float2(acc[mf][nf][2], acc[mf][nf][3]);
        }
    }
}

// ---------------- K4: out = O @ W_out + b ----------------
__global__ __launch_bounds__(256, 2) void k_outproj(const float* __restrict__ bout,
                                                    float* __restrict__ out) {
    extern __shared__ __half sm[];
    __half* Ah = sm;
    __half* Al = sm + 5120;
    __half* Bh = sm + 10240;
    const int tid = threadIdx.x, lane = tid & 31, wid = tid >> 5;
    const int wm = wid & 1, wn = wid >> 1, g = lane >> 2, tg = lane & 3;
    const int bn = blockIdx.x * 128, bm = blockIdx.y * 128;

    float acc[4][4][4] = {};
    const __half* aPH = Ah + (wm*64 + g) * STR32 + 2*tg;
    const __half* aPL = aPH + 5120;
    const __half* bpH = Bh + (wn*32 + g) * STR32 + 2*tg;

    for (int c = 0; c < 32; c++) {
        #pragma unroll
        for (int i = 0; i < 4; i++) {
            int f = tid + i*256, row = f >> 3, c4 = f & 7;
            int m = bm + row, b = m >> 11, t = m & 2047;
            int kk = c*32 + c4*4, hh = kk >> 6, dd = kk & 63;
            float4 va = *(const float4*)(g_o + ((size_t)(b*HH + hh)*TT + t)*HD + dd);
            splitst(Ah, Al, row*STR32 + c4*4, va);
            float4 vb = *(const float4*)(g_woutT + (size_t)(bn+row)*CC + c*32 + c4*4);
            splitst_h(Bh, row*STR32 + c4*4, vb);
        }
        __syncthreads();
        #pragma unroll
        for (int ks = 0; ks < 2; ks++) {
            uint32_t ah[4][4], al[4][4];
            #pragma unroll
            for (int mf = 0; mf < 4; mf++) {
                int off = mf*16*STR32 + ks*16;
                lda(ah[mf], aPH + off, STR32);
                lda(al[mf], aPL + off, STR32);
            }
            #pragma unroll
            for (int nf = 0; nf < 4; nf++) {
                const __half* ph = bpH + nf*8*STR32 + ks*16;
                uint32_t bh0 = *(const uint32_t*)ph, bh1 = *(const uint32_t*)(ph + 8);
                #pragma unroll
                for (int mf = 0; mf < 4; mf++) {
                    mma16816(acc[mf][nf], ah[mf], bh0, bh1);
                    mma16816(acc[mf][nf], al[mf], bh0, bh1);
                }
            }
        }
        __syncthreads();
    }
    #pragma unroll
    for (int mf = 0; mf < 4; mf++) {
        #pragma unroll
        for (int half = 0; half < 2; half++) {
            int m = bm + wm*64 + mf*16 + g + half*8;
            #pragma unroll
            for (int nf = 0; nf < 4; nf++) {
                int n = bn + wn*32 + nf*8 + 2*tg;
                float2 o = make_float2(acc[mf][nf][half*2+0] + bout[n],
                                       acc[mf][nf][half*2+1] + bout[n+1]);
                *(float2*)(out + (size_t)m*CC + n) = o;
            }
        }
    }
}

// ---------------- launch ----------------
extern "C" void kernel_launch(void* const* d_in, const int* in_sizes, int n_in,
                              void* d_out, int out_size) {
    const float* x    = (const float*)d_in[0];
    const float* Wqkv = (const float*)d_in[1];
    const float* Wout = (const float*)d_in[2];
    const float* bout = (const float*)d_in[3];
    float* out  = (float*)d_out;
    float* attn = out + (size_t)BB * TT * CC;

    cudaFuncSetAttribute(k_scores, cudaFuncAttributeMaxDynamicSharedMemorySize, 59392);
    cudaFuncSetAttribute(k_pv,     cudaFuncAttributeMaxDynamicSharedMemorySize, 50176);

    k_rope_tab<<<256, 256>>>();
    k_transpose<<<dim3(C3 / 32, CC / 32), dim3(32, 8)>>>(Wqkv, 0, CC, C3);
    k_transpose<<<dim3(CC / 32, CC / 32), dim3(32, 8)>>>(Wout, 1, CC, CC);
    k_qkv    <<<dim3(C3 / 128, (BB * TT) / 128), 256, 30720>>>(x);
    k_scores <<<dim3(TT / 128, NBH), 256, 59392>>>(attn);
    k_pv     <<<dim3(TT / 256, NBH), 256, 50176>>>(attn);
    k_outproj<<<dim3(CC / 128, (BB * TT) / 128), 256, 30720>>>(bout, out);
}

// round 10
// speedup vs baseline: 2.6314x; 1.3663x over previous
#include <cuda_runtime.h>
#include <cuda_fp16.h>
#include <cstdint>
#include <math.h>

#define BB 2
#define TT 2048
#define CC 1024
#define HH 16
#define HD 64
#define NBH 32
#define C3 3072

// ---------------- device scratch (never passed as kernel args) ----------------
__device__ __half g_xh[BB*TT*CC];
__device__ __half g_xl[BB*TT*CC];
__device__ __half g_wqkvTh[C3*CC];      // [n][k] hi
__device__ __half g_woutTh[CC*CC];      // [n][k] hi
__device__ __half g_qh[NBH*TT*HD];      // [bh][t][d]
__device__ __half g_ql[NBH*TT*HD];
__device__ __half g_kh[NBH*TT*HD];
__device__ __half g_vth[NBH*HD*TT];     // [bh][d][t]
__device__ __half g_oh[NBH*TT*HD];
__device__ __half g_ol[NBH*TT*HD];
__device__ float g_rmax[NBH*TT];
__device__ float g_rinv[NBH*TT];
__device__ float g_cos[TT*32];
__device__ float g_sin[TT*32];

#define STR32 40
#define STR64 72

// ---------------- helpers ----------------
__device__ __forceinline__ uint32_t s2u(const void* p) {
    uint32_t a;
    asm("{ .reg .u64 t; cvta.to.shared.u64 t, %1; cvt.u32.u64 %0, t; }" : "=r"(a) : "l"(p));
    return a;
}
__device__ __forceinline__ void mma16816(float* d, const uint32_t* a, uint32_t b0, uint32_t b1) {
    asm volatile("mma.sync.aligned.m16n8k16.row.col.f32.f16.f16.f32 "
                 "{%0,%1,%2,%3}, {%4,%5,%6,%7}, {%8,%9}, {%0,%1,%2,%3};"
                 : "+f"(d[0]), "+f"(d[1]), "+f"(d[2]), "+f"(d[3])
                 : "r"(a[0]), "r"(a[1]), "r"(a[2]), "r"(a[3]), "r"(b0), "r"(b1));
}
__device__ __forceinline__ void ldm4(uint32_t* r, uint32_t a) {
    asm volatile("ldmatrix.sync.aligned.m8n8.x4.shared.b16 {%0,%1,%2,%3}, [%4];"
                 : "=r"(r[0]), "=r"(r[1]), "=r"(r[2]), "=r"(r[3]) : "r"(a));
}
__device__ __forceinline__ void ldm2(uint32_t* r, uint32_t a) {
    asm volatile("ldmatrix.sync.aligned.m8n8.x2.shared.b16 {%0,%1}, [%2];"
                 : "=r"(r[0]), "=r"(r[1]) : "r"(a));
}
__device__ __forceinline__ __half2 h2hi(float a, float b) {
    return __halves2half2(__float2half_rn(a), __float2half_rn(b));
}
__device__ __forceinline__ __half2 h2lo(float a, float b, __half2 h) {
    return __halves2half2(__float2half_rn(a - __low2float(h)),
                          __float2half_rn(b - __high2float(h)));
}
// split a float4 into fp16 hi/lo and store at half-index idx (for P in k_pv)
__device__ __forceinline__ void splitst(__half* hi, __half* lo, int idx, float4 v) {
    __half2 H0 = h2hi(v.x, v.y), H1 = h2hi(v.z, v.w);
    __half2 L0 = h2lo(v.x, v.y, H0), L1 = h2lo(v.z, v.w, H1);
    uint2 HU, LU;
    HU.x = *reinterpret_cast<uint32_t*>(&H0); HU.y = *reinterpret_cast<uint32_t*>(&H1);
    LU.x = *reinterpret_cast<uint32_t*>(&L0); LU.y = *reinterpret_cast<uint32_t*>(&L1);
    *reinterpret_cast<uint2*>(hi + idx) = HU;
    *reinterpret_cast<uint2*>(lo + idx) = LU;
}

// ---------------- RoPE table ----------------
__global__ void k_rope_tab() {
    int idx = blockIdx.x * 256 + threadIdx.x;
    if (idx >= TT * 32) return;
    int t = idx / 32, j = idx % 32;
    int mi = (2 * j) % 32;
    float inv32 = (float)pow(10000.0, -(double)mi / 32.0);
    float th32 = (float)t * inv32;
    g_cos[idx] = (float)cos((double)th32);
    g_sin[idx] = (float)sin((double)th32);
}

// ---------------- split x into fp16 hi/lo ----------------
__global__ void k_half_x(const float* __restrict__ x) {
    int idx = (blockIdx.x * 256 + threadIdx.x) * 4;
    float4 v = *(const float4*)(x + idx);
    __half2 H0 = h2hi(v.x, v.y), H1 = h2hi(v.z, v.w);
    __half2 L0 = h2lo(v.x, v.y, H0), L1 = h2lo(v.z, v.w, H1);
    uint2 HU, LU;
    HU.x = *reinterpret_cast<uint32_t*>(&H0); HU.y = *reinterpret_cast<uint32_t*>(&H1);
    LU.x = *reinterpret_cast<uint32_t*>(&L0); LU.y = *reinterpret_cast<uint32_t*>(&L1);
    *reinterpret_cast<uint2*>(g_xh + idx) = HU;
    *reinterpret_cast<uint2*>(g_xl + idx) = LU;
}

// ---------------- transpose + fp16 convert: src[K][N] -> dst[N][K] ----------------
__global__ void k_transpose(const float* __restrict__ src, int which, int K, int N) {
    __shared__ float tb[32][33];
    __half* dst = which ? g_woutTh : g_wqkvTh;
    int n0 = blockIdx.x * 32, k0 = blockIdx.y * 32;
    for (int i = threadIdx.y; i < 32; i += 8)
        tb[i][threadIdx.x] = src[(size_t)(k0 + i) * N + n0 + threadIdx.x];
    __syncthreads();
    for (int i = threadIdx.y; i < 32; i += 8)
        dst[(size_t)(n0 + i) * K + k0 + threadIdx.x] = __float2half_rn(tb[threadIdx.x][i]);
}

// ---------------- K1: QKV GEMM (HMMA 2-pass) + RoPE + scatter ----------------
__global__ __launch_bounds__(256, 2) void k_qkv() {
    extern __shared__ __half sm[];
    __half* Ah = sm;            // 128*40
    __half* Al = sm + 5120;
    __half* Bh = sm + 10240;
    const int tid = threadIdx.x, lane = tid & 31, wid = tid >> 5;
    const int wm = wid & 1, wn = wid >> 1, g = lane >> 2, tg = lane & 3;
    const int bn = blockIdx.x * 128, bm = blockIdx.y * 128;
    const int l15 = lane & 15;

    float acc[4][4][4] = {};
    const uint32_t aBaseH = s2u(Ah) + (((wm*64 + l15) * STR32 + (lane >> 4) * 8) << 1);
    const uint32_t aBaseL = aBaseH + 5120 * 2;
    const uint32_t bBase  = s2u(Bh) + (((wn*32 + (l15 & 7)) * STR32 + (l15 >> 3) * 8) << 1);

    for (int c = 0; c < 32; c++) {
        #pragma unroll
        for (int i = 0; i < 2; i++) {
            int f = tid + i*256, row = f >> 2, c8 = f & 3;
            size_t go = (size_t)(bm+row)*CC + c*32 + c8*8;
            *(uint4*)(Ah + row*STR32 + c8*8) = *(const uint4*)(g_xh + go);
            *(uint4*)(Al + row*STR32 + c8*8) = *(const uint4*)(g_xl + go);
            *(uint4*)(Bh + row*STR32 + c8*8) = *(const uint4*)(g_wqkvTh + (size_t)(bn+row)*CC + c*32 + c8*8);
        }
        __syncthreads();
        #pragma unroll
        for (int ks = 0; ks < 2; ks++) {
            uint32_t ah[4][4], al[4][4], bf[4][2];
            #pragma unroll
            for (int mf = 0; mf < 4; mf++) {
                uint32_t off = (uint32_t)((mf*16*STR32 + ks*16) << 1);
                ldm4(ah[mf], aBaseH + off);
                ldm4(al[mf], aBaseL + off);
            }
            #pragma unroll
            for (int nf = 0; nf < 4; nf++)
                ldm2(bf[nf], bBase + (uint32_t)((nf*8*STR32 + ks*16) << 1));
            #pragma unroll
            for (int nf = 0; nf < 4; nf++)
                #pragma unroll
                for (int mf = 0; mf < 4; mf++) {
                    mma16816(acc[mf][nf], ah[mf], bf[nf][0], bf[nf][1]);
                    mma16816(acc[mf][nf], al[mf], bf[nf][0], bf[nf][1]);
                }
        }
        __syncthreads();
    }
    #pragma unroll
    for (int mf = 0; mf < 4; mf++) {
        #pragma unroll
        for (int half = 0; half < 2; half++) {
            int m = bm + wm*64 + mf*16 + g + half*8;
            int b = m >> 11, t = m & 2047;
            #pragma unroll
            for (int nf = 0; nf < 4; nf++) {
                int n = bn + wn*32 + nf*8 + 2*tg;
                float v0 = acc[mf][nf][half*2 + 0], v1 = acc[mf][nf][half*2 + 1];
                int sect = n >> 10, rem = n & 1023, hh = rem >> 6, d = rem & 63;
                if (sect == 2) {
                    size_t base = ((size_t)(b*HH + hh) * HD + d) * TT + t;
                    g_vth[base] = __float2half_rn(v0);
                    g_vth[base + TT] = __float2half_rn(v1);
                } else {
                    int j2 = d >> 1;
                    float cs = g_cos[t*32 + j2], sn = g_sin[t*32 + j2];
                    float r0 = v0*cs - v1*sn, r1 = v1*cs + v0*sn;
                    size_t idx = ((size_t)(b*HH + hh)*TT + t)*HD + d;
                    __half2 hi = h2hi(r0, r1);
                    if (sect == 0) {
                        *(__half2*)(g_qh + idx) = hi;
                        *(__half2*)(g_ql + idx) = h2lo(r0, r1, hi);
                    } else {
                        *(__half2*)(g_kh + idx) = hi;
                    }
                }
            }
        }
    }
}

// ---------------- K2: scores = QK^T/8 - alibi + fused flash row stats ----------------
__global__ __launch_bounds__(256, 2) void k_scores(float* __restrict__ attn) {
    extern __shared__ __half sm[];
    __half* Qh = sm;                // 128*72
    __half* Ql = sm + 9216;
    __half* Kh = sm + 18432;
    float* srd_m = (float*)(sm + 27648);   // [4][128]
    float* srd_s = srd_m + 512;
    const int tid = threadIdx.x, lane = tid & 31, wid = tid >> 5;
    const int wm = wid & 1, wn = wid >> 1, g = lane >> 2, tg = lane & 3;
    const int bh = blockIdx.y, h = bh & 15, q0 = blockIdx.x * 128;
    const int l15 = lane & 15;
    const __half* qhb = g_qh + (size_t)bh * TT * HD;
    const __half* qlb = g_ql + (size_t)bh * TT * HD;
    const __half* khb = g_kh + (size_t)bh * TT * HD;

    #pragma unroll
    for (int i = 0; i < 4; i++) {
        int f = tid + i*256, row = f >> 3, c8 = f & 7;
        size_t go = (size_t)(q0+row)*HD + c8*8;
        *(uint4*)(Qh + row*STR64 + c8*8) = *(const uint4*)(qhb + go);
        *(uint4*)(Ql + row*STR64 + c8*8) = *(const uint4*)(qlb + go);
    }
    const uint32_t aBaseH = s2u(Qh) + (((wm*64 + l15) * STR64 + (lane >> 4) * 8) << 1);
    const uint32_t aBaseL = aBaseH + 9216 * 2;
    const uint32_t bBase  = s2u(Kh) + (((wn*32 + (l15 & 7)) * STR64 + (l15 >> 3) * 8) << 1);
    const float slope = exp2f(-0.5f * (float)(h + 1));
    float rm[8], rs[8];
    #pragma unroll
    for (int i = 0; i < 8; i++) { rm[i] = -INFINITY; rs[i] = 0.f; }

    for (int nt = 0; nt < 16; nt++) {
        #pragma unroll
        for (int i = 0; i < 4; i++) {
            int f = tid + i*256, row = f >> 3, c8 = f & 7;
            *(uint4*)(Kh + row*STR64 + c8*8) = *(const uint4*)(khb + (size_t)(nt*128+row)*HD + c8*8);
        }
        __syncthreads();
        float acc[4][4][4] = {};
        #pragma unroll
        for (int ks = 0; ks < 4; ks++) {
            uint32_t ah[4][4], al[4][4], bf[4][2];
            #pragma unroll
            for (int mf = 0; mf < 4; mf++) {
                uint32_t off = (uint32_t)((mf*16*STR64 + ks*16) << 1);
                ldm4(ah[mf], aBaseH + off);
                ldm4(al[mf], aBaseL + off);
            }
            #pragma unroll
            for (int nf = 0; nf < 4; nf++)
                ldm2(bf[nf], bBase + (uint32_t)((nf*8*STR64 + ks*16) << 1));
            #pragma unroll
            for (int nf = 0; nf < 4; nf++)
                #pragma unroll
                for (int mf = 0; mf < 4; mf++) {
                    mma16816(acc[mf][nf], ah[mf], bf[nf][0], bf[nf][1]);
                    mma16816(acc[mf][nf], al[mf], bf[nf][0], bf[nf][1]);
                }
        }
        #pragma unroll
        for (int mf = 0; mf < 4; mf++) {
            #pragma unroll
            for (int half = 0; half < 2; half++) {
                int r = wm*64 + mf*16 + g + half*8;
                int q = q0 + r;
                float vv[8];
                float tmax = -INFINITY;
                #pragma unroll
                for (int nf = 0; nf < 4; nf++) {
                    int col = nt*128 + wn*32 + nf*8 + 2*tg;
                    float v0 = acc[mf][nf][half*2+0] * 0.125f - slope * fabsf((float)(q - col));
                    float v1 = acc[mf][nf][half*2+1] * 0.125f - slope * fabsf((float)(q - col - 1));
                    vv[nf*2] = v0; vv[nf*2+1] = v1;
                    *(float2*)(attn + ((size_t)bh*TT + q)*TT + col) = make_float2(v0, v1);
                    tmax = fmaxf(tmax, fmaxf(v0, v1));
                }
                int ri = mf*2 + half;
                float nm = fmaxf(rm[ri], tmax);
                float s = 0.f;
                #pragma unroll
                for (int j = 0; j < 8; j++) s += __expf(vv[j] - nm);
                rs[ri] = rs[ri] * __expf(rm[ri] - nm) + s;
                rm[ri] = nm;
            }
        }
        __syncthreads();
    }
    #pragma unroll
    for (int i = 0; i < 8; i++) {
        #pragma unroll
        for (int dd = 1; dd < 4; dd <<= 1) {
            float om = __shfl_xor_sync(0xffffffffu, rm[i], dd);
            float os = __shfl_xor_sync(0xffffffffu, rs[i], dd);
            float nm = fmaxf(rm[i], om);
            rs[i] = rs[i] * __expf(rm[i] - nm) + os * __expf(om - nm);
            rm[i] = nm;
        }
    }
    if (tg == 0) {
        #pragma unroll
        for (int mf = 0; mf < 4; mf++)
            #pragma unroll
            for (int half = 0; half < 2; half++) {
                int r = wm*64 + mf*16 + g + half*8;
                srd_m[wn*128 + r] = rm[mf*2 + half];
                srd_s[wn*128 + r] = rs[mf*2 + half];
            }
    }
    __syncthreads();
    if (tid < 128) {
        float m = srd_m[tid], s = srd_s[tid];
        #pragma unroll
        for (int w = 1; w < 4; w++) {
            float om = srd_m[w*128 + tid], os = srd_s[w*128 + tid];
            float nm = fmaxf(m, om);
            s = s * __expf(m - nm) + os * __expf(om - nm);
            m = nm;
        }
        g_rmax[(size_t)bh*TT + q0 + tid] = m;
        g_rinv[(size_t)bh*TT + q0 + tid] = 1.0f / s;
    }
}

// ---------------- K3: normalize P (final attn) + O = P @ V ----------------
__global__ __launch_bounds__(256, 2) void k_pv(float* __restrict__ attn) {
    extern __shared__ __half sm[];
    __half* Ph = sm;              // 256*40
    __half* Pl = sm + 10240;
    __half* Vh = sm + 20480;      // 64*40
    float* srm = (float*)(sm + 23040);   // 256
    float* sri = srm + 256;
    const int tid = threadIdx.x, lane = tid & 31, wid = tid >> 5;
    const int wm = wid & 3, wn = wid >> 2, g = lane >> 2, tg = lane & 3;
    const int bh = blockIdx.y, q0 = blockIdx.x * 256;
    const int l15 = lane & 15;
    srm[tid] = g_rmax[(size_t)bh*TT + q0 + tid];
    sri[tid] = g_rinv[(size_t)bh*TT + q0 + tid];
    __syncthreads();
    float acc[4][4][4] = {};
    const uint32_t aBaseH = s2u(Ph) + (((wm*64 + l15) * STR32 + (lane >> 4) * 8) << 1);
    const uint32_t aBaseL = aBaseH + 10240 * 2;
    const uint32_t bBase  = s2u(Vh) + (((wn*32 + (l15 & 7)) * STR32 + (l15 >> 3) * 8) << 1);
    const __half* vtb = g_vth + (size_t)bh * HD * TT;

    for (int c = 0; c < 64; c++) {
        #pragma unroll
        for (int i = 0; i < 8; i++) {
            int f = tid + i*256, row = f >> 3, c4 = f & 7;
            size_t off = ((size_t)bh*TT + q0 + row)*TT + c*32 + c4*4;
            float4 v = *(const float4*)(attn + off);
            float m = srm[row], iv = sri[row];
            float4 p;
            p.x = __expf(v.x - m) * iv;
            p.y = __expf(v.y - m) * iv;
            p.z = __expf(v.z - m) * iv;
            p.w = __expf(v.w - m) * iv;
            *(float4*)(attn + off) = p;               // final attn output
            splitst(Ph, Pl, row*STR32 + c4*4, p);
        }
        {
            int row = tid >> 2, c8 = tid & 3;          // 64 rows x 4 chunks
            *(uint4*)(Vh + row*STR32 + c8*8) = *(const uint4*)(vtb + (size_t)row*TT + c*32 + c8*8);
        }
        __syncthreads();
        #pragma unroll
        for (int ks = 0; ks < 2; ks++) {
            uint32_t ah[4][4], al[4][4], bf[4][2];
            #pragma unroll
            for (int mf = 0; mf < 4; mf++) {
                uint32_t off = (uint32_t)((mf*16*STR32 + ks*16) << 1);
                ldm4(ah[mf], aBaseH + off);
                ldm4(al[mf], aBaseL + off);
            }
            #pragma unroll
            for (int nf = 0; nf < 4; nf++)
                ldm2(bf[nf], bBase + (uint32_t)((nf*8*STR32 + ks*16) << 1));
            #pragma unroll
            for (int nf = 0; nf < 4; nf++)
                #pragma unroll
                for (int mf = 0; mf < 4; mf++) {
                    mma16816(acc[mf][nf], ah[mf], bf[nf][0], bf[nf][1]);
                    mma16816(acc[mf][nf], al[mf], bf[nf][0], bf[nf][1]);
                }
        }
        __syncthreads();
    }
    #pragma unroll
    for (int mf = 0; mf < 4; mf++) {
        int r = q0 + wm*64 + mf*16 + g;
        #pragma unroll
        for (int nf = 0; nf < 4; nf++) {
            int ccol = wn*32 + nf*8 + 2*tg;
            size_t i0 = ((size_t)bh*TT + r)*HD + ccol;
            size_t i1 = ((size_t)bh*TT + r + 8)*HD + ccol;
            __half2 h0 = h2hi(acc[mf][nf][0], acc[mf][nf][1]);
            __half2 h1 = h2hi(acc[mf][nf][2], acc[mf][nf][3]);
            *(__half2*)(g_oh + i0) = h0;
            *(__half2*)(g_ol + i0) = h2lo(acc[mf][nf][0], acc[mf][nf][1], h0);
            *(__half2*)(g_oh + i1) = h1;
            *(__half2*)(g_ol + i1) = h2lo(acc[mf][nf][2], acc[mf][nf][3], h1);
        }
    }
}

// ---------------- K4: out = O @ W_out + b ----------------
__global__ __launch_bounds__(256, 2) void k_outproj(const float* __restrict__ bout,
                                                    float* __restrict__ out) {
    extern __shared__ __half sm[];
    __half* Ah = sm;
    __half* Al = sm + 5120;
    __half* Bh = sm + 10240;
    const int tid = threadIdx.x, lane = tid & 31, wid = tid >> 5;
    const int wm = wid & 1, wn = wid >> 1, g = lane >> 2, tg = lane & 3;
    const int bn = blockIdx.x * 128, bm = blockIdx.y * 128;
    const int l15 = lane & 15;

    float acc[4][4][4] = {};
    const uint32_t aBaseH = s2u(Ah) + (((wm*64 + l15) * STR32 + (lane >> 4) * 8) << 1);
    const uint32_t aBaseL = aBaseH + 5120 * 2;
    const uint32_t bBase  = s2u(Bh) + (((wn*32 + (l15 & 7)) * STR32 + (l15 >> 3) * 8) << 1);

    for (int c = 0; c < 32; c++) {
        #pragma unroll
        for (int i = 0; i < 2; i++) {
            int f = tid + i*256, row = f >> 2, c8 = f & 3;
            int m = bm + row, b = m >> 11, t = m & 2047;
            int kk = c*32 + c8*8, hh = kk >> 6, dd = kk & 63;
            size_t go = ((size_t)(b*HH + hh)*TT + t)*HD + dd;
            *(uint4*)(Ah + row*STR32 + c8*8) = *(const uint4*)(g_oh + go);
            *(uint4*)(Al + row*STR32 + c8*8) = *(const uint4*)(g_ol + go);
            *(uint4*)(Bh + row*STR32 + c8*8) = *(const uint4*)(g_woutTh + (size_t)(bn+row)*CC + c*32 + c8*8);
        }
        __syncthreads();
        #pragma unroll
        for (int ks = 0; ks < 2; ks++) {
            uint32_t ah[4][4], al[4][4], bf[4][2];
            #pragma unroll
            for (int mf = 0; mf < 4; mf++) {
                uint32_t off = (uint32_t)((mf*16*STR32 + ks*16) << 1);
                ldm4(ah[mf], aBaseH + off);
                ldm4(al[mf], aBaseL + off);
            }
            #pragma unroll
            for (int nf = 0; nf < 4; nf++)
                ldm2(bf[nf], bBase + (uint32_t)((nf*8*STR32 + ks*16) << 1));
            #pragma unroll
            for (int nf = 0; nf < 4; nf++)
                #pragma unroll
                for (int mf = 0; mf < 4; mf++) {
                    mma16816(acc[mf][nf], ah[mf], bf[nf][0], bf[nf][1]);
                    mma16816(acc[mf][nf], al[mf], bf[nf][0], bf[nf][1]);
                }
        }
        __syncthreads();
    }
    #pragma unroll
    for (int mf = 0; mf < 4; mf++) {
        #pragma unroll
        for (int half = 0; half < 2; half++) {
            int m = bm + wm*64 + mf*16 + g + half*8;
            #pragma unroll
            for (int nf = 0; nf < 4; nf++) {
                int n = bn + wn*32 + nf*8 + 2*tg;
                float2 o = make_float2(acc[mf][nf][half*2+0] + bout[n],
                                       acc[mf][nf][half*2+1] + bout[n+1]);
                *(float2*)(out + (size_t)m*CC + n) = o;
            }
        }
    }
}

// ---------------- launch ----------------
extern "C" void kernel_launch(void* const* d_in, const int* in_sizes, int n_in,
                              void* d_out, int out_size) {
    const float* x    = (const float*)d_in[0];
    const float* Wqkv = (const float*)d_in[1];
    const float* Wout = (const float*)d_in[2];
    const float* bout = (const float*)d_in[3];
    float* out  = (float*)d_out;
    float* attn = out + (size_t)BB * TT * CC;

    cudaFuncSetAttribute(k_scores, cudaFuncAttributeMaxDynamicSharedMemorySize, 59392);
    cudaFuncSetAttribute(k_pv,     cudaFuncAttributeMaxDynamicSharedMemorySize, 48128);

    k_rope_tab<<<256, 256>>>();
    k_half_x<<<(BB*TT*CC)/1024, 256>>>(x);
    k_transpose<<<dim3(C3 / 32, CC / 32), dim3(32, 8)>>>(Wqkv, 0, CC, C3);
    k_transpose<<<dim3(CC / 32, CC / 32), dim3(32, 8)>>>(Wout, 1, CC, CC);
    k_qkv    <<<dim3(C3 / 128, (BB * TT) / 128), 256, 30720>>>();
    k_scores <<<dim3(TT / 128, NBH), 256, 59392>>>(attn);
    k_pv     <<<dim3(TT / 256, NBH), 256, 48128>>>(attn);
    k_outproj<<<dim3(CC / 128, (BB * TT) / 128), 256, 30720>>>(bout, out);
}

// round 11
// speedup vs baseline: 2.7258x; 1.0359x over previous
#include <cuda_runtime.h>
#include <cuda_fp16.h>
#include <cstdint>
#include <math.h>

#define BB 2
#define TT 2048
#define CC 1024
#define HH 16
#define HD 64
#define NBH 32
#define C3 3072

// ---------------- device scratch (never passed as kernel args) ----------------
__device__ __half g_xh[BB*TT*CC];
__device__ __half g_xl[BB*TT*CC];
__device__ __half g_wqkvTh[C3*CC];      // [n][k] hi
__device__ __half g_woutTh[CC*CC];      // [n][k] hi
__device__ __half g_qh[NBH*TT*HD];      // [bh][t][d]
__device__ __half g_ql[NBH*TT*HD];
__device__ __half g_kh[NBH*TT*HD];
__device__ __half g_vth[NBH*HD*TT];     // [bh][d][t]
__device__ __half g_oh[NBH*TT*HD];
__device__ __half g_ol[NBH*TT*HD];
__device__ float g_rinv[NBH*TT];
__device__ float g_cos[TT*32];
__device__ float g_sin[TT*32];

#define STR32 40
#define STR64 72

// ---------------- helpers ----------------
__device__ __forceinline__ uint32_t s2u(const void* p) {
    uint32_t a;
    asm("{ .reg .u64 t; cvta.to.shared.u64 t, %1; cvt.u32.u64 %0, t; }" : "=r"(a) : "l"(p));
    return a;
}
__device__ __forceinline__ void mma16816(float* d, const uint32_t* a, uint32_t b0, uint32_t b1) {
    asm volatile("mma.sync.aligned.m16n8k16.row.col.f32.f16.f16.f32 "
                 "{%0,%1,%2,%3}, {%4,%5,%6,%7}, {%8,%9}, {%0,%1,%2,%3};"
                 : "+f"(d[0]), "+f"(d[1]), "+f"(d[2]), "+f"(d[3])
                 : "r"(a[0]), "r"(a[1]), "r"(a[2]), "r"(a[3]), "r"(b0), "r"(b1));
}
__device__ __forceinline__ void ldm4(uint32_t* r, uint32_t a) {
    asm volatile("ldmatrix.sync.aligned.m8n8.x4.shared.b16 {%0,%1,%2,%3}, [%4];"
                 : "=r"(r[0]), "=r"(r[1]), "=r"(r[2]), "=r"(r[3]) : "r"(a));
}
__device__ __forceinline__ void ldm2(uint32_t* r, uint32_t a) {
    asm volatile("ldmatrix.sync.aligned.m8n8.x2.shared.b16 {%0,%1}, [%2];"
                 : "=r"(r[0]), "=r"(r[1]) : "r"(a));
}
__device__ __forceinline__ __half2 h2hi(float a, float b) {
    return __halves2half2(__float2half_rn(a), __float2half_rn(b));
}
__device__ __forceinline__ __half2 h2lo(float a, float b, __half2 h) {
    return __halves2half2(__float2half_rn(a - __low2float(h)),
                          __float2half_rn(b - __high2float(h)));
}
// split a float4 into fp16 hi/lo and store at half-index idx
__device__ __forceinline__ void splitst(__half* hi, __half* lo, int idx, float4 v) {
    __half2 H0 = h2hi(v.x, v.y), H1 = h2hi(v.z, v.w);
    __half2 L0 = h2lo(v.x, v.y, H0), L1 = h2lo(v.z, v.w, H1);
    uint2 HU, LU;
    HU.x = *reinterpret_cast<uint32_t*>(&H0); HU.y = *reinterpret_cast<uint32_t*>(&H1);
    LU.x = *reinterpret_cast<uint32_t*>(&L0); LU.y = *reinterpret_cast<uint32_t*>(&L1);
    *reinterpret_cast<uint2*>(hi + idx) = HU;
    *reinterpret_cast<uint2*>(lo + idx) = LU;
}

// ---------------- RoPE table ----------------
__global__ void k_rope_tab() {
    int idx = blockIdx.x * 256 + threadIdx.x;
    if (idx >= TT * 32) return;
    int t = idx / 32, j = idx % 32;
    int mi = (2 * j) % 32;
    float inv32 = (float)pow(10000.0, -(double)mi / 32.0);
    float th32 = (float)t * inv32;
    g_cos[idx] = (float)cos((double)th32);
    g_sin[idx] = (float)sin((double)th32);
}

// ---------------- split x into fp16 hi/lo ----------------
__global__ void k_half_x(const float* __restrict__ x) {
    int idx = (blockIdx.x * 256 + threadIdx.x) * 4;
    float4 v = *(const float4*)(x + idx);
    __half2 H0 = h2hi(v.x, v.y), H1 = h2hi(v.z, v.w);
    __half2 L0 = h2lo(v.x, v.y, H0), L1 = h2lo(v.z, v.w, H1);
    uint2 HU, LU;
    HU.x = *reinterpret_cast<uint32_t*>(&H0); HU.y = *reinterpret_cast<uint32_t*>(&H1);
    LU.x = *reinterpret_cast<uint32_t*>(&L0); LU.y = *reinterpret_cast<uint32_t*>(&L1);
    *reinterpret_cast<uint2*>(g_xh + idx) = HU;
    *reinterpret_cast<uint2*>(g_xl + idx) = LU;
}

// ---------------- transpose + fp16 convert: src[K][N] -> dst[N][K] ----------------
__global__ void k_transpose(const float* __restrict__ src, int which, int K, int N) {
    __shared__ float tb[32][33];
    __half* dst = which ? g_woutTh : g_wqkvTh;
    int n0 = blockIdx.x * 32, k0 = blockIdx.y * 32;
    for (int i = threadIdx.y; i < 32; i += 8)
        tb[i][threadIdx.x] = src[(size_t)(k0 + i) * N + n0 + threadIdx.x];
    __syncthreads();
    for (int i = threadIdx.y; i < 32; i += 8)
        dst[(size_t)(n0 + i) * K + k0 + threadIdx.x] = __float2half_rn(tb[threadIdx.x][i]);
}

// ---------------- K1: QKV GEMM (HMMA 2-pass) + RoPE + scatter ----------------
__global__ __launch_bounds__(256, 2) void k_qkv() {
    extern __shared__ __half sm[];
    __half* Ah = sm;            // 128*40
    __half* Al = sm + 5120;
    __half* Bh = sm + 10240;
    const int tid = threadIdx.x, lane = tid & 31, wid = tid >> 5;
    const int wm = wid & 1, wn = wid >> 1, g = lane >> 2, tg = lane & 3;
    const int bn = blockIdx.x * 128, bm = blockIdx.y * 128;
    const int l15 = lane & 15;

    float acc[4][4][4] = {};
    const uint32_t aBaseH = s2u(Ah) + (((wm*64 + l15) * STR32 + (lane >> 4) * 8) << 1);
    const uint32_t aBaseL = aBaseH + 5120 * 2;
    const uint32_t bBase  = s2u(Bh) + (((wn*32 + (l15 & 7)) * STR32 + (l15 >> 3) * 8) << 1);

    for (int c = 0; c < 32; c++) {
        #pragma unroll
        for (int i = 0; i < 2; i++) {
            int f = tid + i*256, row = f >> 2, c8 = f & 3;
            size_t go = (size_t)(bm+row)*CC + c*32 + c8*8;
            *(uint4*)(Ah + row*STR32 + c8*8) = *(const uint4*)(g_xh + go);
            *(uint4*)(Al + row*STR32 + c8*8) = *(const uint4*)(g_xl + go);
            *(uint4*)(Bh + row*STR32 + c8*8) = *(const uint4*)(g_wqkvTh + (size_t)(bn+row)*CC + c*32 + c8*8);
        }
        __syncthreads();
        #pragma unroll
        for (int ks = 0; ks < 2; ks++) {
            uint32_t ah[4][4], al[4][4], bf[4][2];
            #pragma unroll
            for (int mf = 0; mf < 4; mf++) {
                uint32_t off = (uint32_t)((mf*16*STR32 + ks*16) << 1);
                ldm4(ah[mf], aBaseH + off);
                ldm4(al[mf], aBaseL + off);
            }
            #pragma unroll
            for (int nf = 0; nf < 4; nf++)
                ldm2(bf[nf], bBase + (uint32_t)((nf*8*STR32 + ks*16) << 1));
            #pragma unroll
            for (int nf = 0; nf < 4; nf++)
                #pragma unroll
                for (int mf = 0; mf < 4; mf++) {
                    mma16816(acc[mf][nf], ah[mf], bf[nf][0], bf[nf][1]);
                    mma16816(acc[mf][nf], al[mf], bf[nf][0], bf[nf][1]);
                }
        }
        __syncthreads();
    }
    #pragma unroll
    for (int mf = 0; mf < 4; mf++) {
        #pragma unroll
        for (int half = 0; half < 2; half++) {
            int m = bm + wm*64 + mf*16 + g + half*8;
            int b = m >> 11, t = m & 2047;
            #pragma unroll
            for (int nf = 0; nf < 4; nf++) {
                int n = bn + wn*32 + nf*8 + 2*tg;
                float v0 = acc[mf][nf][half*2 + 0], v1 = acc[mf][nf][half*2 + 1];
                int sect = n >> 10, rem = n & 1023, hh = rem >> 6, d = rem & 63;
                if (sect == 2) {
                    size_t base = ((size_t)(b*HH + hh) * HD + d) * TT + t;
                    g_vth[base] = __float2half_rn(v0);
                    g_vth[base + TT] = __float2half_rn(v1);
                } else {
                    int j2 = d >> 1;
                    float cs = g_cos[t*32 + j2], sn = g_sin[t*32 + j2];
                    float r0 = v0*cs - v1*sn, r1 = v1*cs + v0*sn;
                    size_t idx = ((size_t)(b*HH + hh)*TT + t)*HD + d;
                    __half2 hi = h2hi(r0, r1);
                    if (sect == 0) {
                        *(__half2*)(g_qh + idx) = hi;
                        *(__half2*)(g_ql + idx) = h2lo(r0, r1, hi);
                    } else {
                        *(__half2*)(g_kh + idx) = hi;
                    }
                }
            }
        }
    }
}

// ---------------- K2: attn <- exp(QK^T/8 - alibi); g_rinv <- 1/rowsum ----------------
__global__ __launch_bounds__(256, 2) void k_scores(float* __restrict__ attn) {
    extern __shared__ __half sm[];
    __half* Qh = sm;                // 128*72
    __half* Ql = sm + 9216;
    __half* Kh = sm + 18432;
    float* srd_s = (float*)(sm + 27648);   // [4][128]
    const int tid = threadIdx.x, lane = tid & 31, wid = tid >> 5;
    const int wm = wid & 1, wn = wid >> 1, g = lane >> 2, tg = lane & 3;
    const int bh = blockIdx.y, h = bh & 15, q0 = blockIdx.x * 128;
    const int l15 = lane & 15;
    const __half* qhb = g_qh + (size_t)bh * TT * HD;
    const __half* qlb = g_ql + (size_t)bh * TT * HD;
    const __half* khb = g_kh + (size_t)bh * TT * HD;

    #pragma unroll
    for (int i = 0; i < 4; i++) {
        int f = tid + i*256, row = f >> 3, c8 = f & 7;
        size_t go = (size_t)(q0+row)*HD + c8*8;
        *(uint4*)(Qh + row*STR64 + c8*8) = *(const uint4*)(qhb + go);
        *(uint4*)(Ql + row*STR64 + c8*8) = *(const uint4*)(qlb + go);
    }
    const uint32_t aBaseH = s2u(Qh) + (((wm*64 + l15) * STR64 + (lane >> 4) * 8) << 1);
    const uint32_t aBaseL = aBaseH + 9216 * 2;
    const uint32_t bBase  = s2u(Kh) + (((wn*32 + (l15 & 7)) * STR64 + (l15 >> 3) * 8) << 1);
    const float slope = exp2f(-0.5f * (float)(h + 1));
    float rs[8];
    #pragma unroll
    for (int i = 0; i < 8; i++) rs[i] = 0.f;

    for (int nt = 0; nt < 16; nt++) {
        #pragma unroll
        for (int i = 0; i < 4; i++) {
            int f = tid + i*256, row = f >> 3, c8 = f & 7;
            *(uint4*)(Kh + row*STR64 + c8*8) = *(const uint4*)(khb + (size_t)(nt*128+row)*HD + c8*8);
        }
        __syncthreads();
        float acc[4][4][4] = {};
        #pragma unroll
        for (int ks = 0; ks < 4; ks++) {
            uint32_t ah[4][4], al[4][4], bf[4][2];
            #pragma unroll
            for (int mf = 0; mf < 4; mf++) {
                uint32_t off = (uint32_t)((mf*16*STR64 + ks*16) << 1);
                ldm4(ah[mf], aBaseH + off);
                ldm4(al[mf], aBaseL + off);
            }
            #pragma unroll
            for (int nf = 0; nf < 4; nf++)
                ldm2(bf[nf], bBase + (uint32_t)((nf*8*STR64 + ks*16) << 1));
            #pragma unroll
            for (int nf = 0; nf < 4; nf++)
                #pragma unroll
                for (int mf = 0; mf < 4; mf++) {
                    mma16816(acc[mf][nf], ah[mf], bf[nf][0], bf[nf][1]);
                    mma16816(acc[mf][nf], al[mf], bf[nf][0], bf[nf][1]);
                }
        }
        #pragma unroll
        for (int mf = 0; mf < 4; mf++) {
            #pragma unroll
            for (int half = 0; half < 2; half++) {
                int r = wm*64 + mf*16 + g + half*8;
                int q = q0 + r;
                float ssum = 0.f;
                #pragma unroll
                for (int nf = 0; nf < 4; nf++) {
                    int col = nt*128 + wn*32 + nf*8 + 2*tg;
                    float e0 = __expf(acc[mf][nf][half*2+0] * 0.125f - slope * fabsf((float)(q - col)));
                    float e1 = __expf(acc[mf][nf][half*2+1] * 0.125f - slope * fabsf((float)(q - col - 1)));
                    *(float2*)(attn + ((size_t)bh*TT + q)*TT + col) = make_float2(e0, e1);
                    ssum += e0 + e1;
                }
                rs[mf*2 + half] += ssum;
            }
        }
        __syncthreads();
    }
    // reduce sums across tg lanes (xor 1,2), then across wn via smem
    #pragma unroll
    for (int i = 0; i < 8; i++) {
        rs[i] += __shfl_xor_sync(0xffffffffu, rs[i], 1);
        rs[i] += __shfl_xor_sync(0xffffffffu, rs[i], 2);
    }
    if (tg == 0) {
        #pragma unroll
        for (int mf = 0; mf < 4; mf++)
            #pragma unroll
            for (int half = 0; half < 2; half++) {
                int r = wm*64 + mf*16 + g + half*8;
                srd_s[wn*128 + r] = rs[mf*2 + half];
            }
    }
    __syncthreads();
    if (tid < 128) {
        float s = srd_s[tid] + srd_s[128 + tid] + srd_s[256 + tid] + srd_s[384 + tid];
        g_rinv[(size_t)bh*TT + q0 + tid] = 1.0f / s;
    }
}

// ---------------- K3: P = E * rinv (final attn) + O = P @ V ----------------
__global__ __launch_bounds__(256, 2) void k_pv(float* __restrict__ attn) {
    extern __shared__ __half sm[];
    __half* Ph = sm;              // 256*40
    __half* Pl = sm + 10240;
    __half* Vh = sm + 20480;      // 64*40
    float* sri = (float*)(sm + 23040);   // 256
    const int tid = threadIdx.x, lane = tid & 31, wid = tid >> 5;
    const int wm = wid & 3, wn = wid >> 2, g = lane >> 2, tg = lane & 3;
    const int bh = blockIdx.y, q0 = blockIdx.x * 256;
    const int l15 = lane & 15;
    sri[tid] = g_rinv[(size_t)bh*TT + q0 + tid];
    __syncthreads();
    float acc[4][4][4] = {};
    const uint32_t aBaseH = s2u(Ph) + (((wm*64 + l15) * STR32 + (lane >> 4) * 8) << 1);
    const uint32_t aBaseL = aBaseH + 10240 * 2;
    const uint32_t bBase  = s2u(Vh) + (((wn*32 + (l15 & 7)) * STR32 + (l15 >> 3) * 8) << 1);
    const __half* vtb = g_vth + (size_t)bh * HD * TT;

    for (int c = 0; c < 64; c++) {
        #pragma unroll
        for (int i = 0; i < 8; i++) {
            int f = tid + i*256, row = f >> 3, c4 = f & 7;
            size_t off = ((size_t)bh*TT + q0 + row)*TT + c*32 + c4*4;
            float4 v = *(const float4*)(attn + off);
            float iv = sri[row];
            float4 p;
            p.x = v.x * iv;
            p.y = v.y * iv;
            p.z = v.z * iv;
            p.w = v.w * iv;
            *(float4*)(attn + off) = p;               // final attn output
            splitst(Ph, Pl, row*STR32 + c4*4, p);
        }
        {
            int row = tid >> 2, c8 = tid & 3;          // 64 rows x 4 chunks
            *(uint4*)(Vh + row*STR32 + c8*8) = *(const uint4*)(vtb + (size_t)row*TT + c*32 + c8*8);
        }
        __syncthreads();
        #pragma unroll
        for (int ks = 0; ks < 2; ks++) {
            uint32_t ah[4][4], al[4][4], bf[4][2];
            #pragma unroll
            for (int mf = 0; mf < 4; mf++) {
                uint32_t off = (uint32_t)((mf*16*STR32 + ks*16) << 1);
                ldm4(ah[mf], aBaseH + off);
                ldm4(al[mf], aBaseL + off);
            }
            #pragma unroll
            for (int nf = 0; nf < 4; nf++)
                ldm2(bf[nf], bBase + (uint32_t)((nf*8*STR32 + ks*16) << 1));
            #pragma unroll
            for (int nf = 0; nf < 4; nf++)
                #pragma unroll
                for (int mf = 0; mf < 4; mf++) {
                    mma16816(acc[mf][nf], ah[mf], bf[nf][0], bf[nf][1]);
                    mma16816(acc[mf][nf], al[mf], bf[nf][0], bf[nf][1]);
                }
        }
        __syncthreads();
    }
    #pragma unroll
    for (int mf = 0; mf < 4; mf++) {
        int r = q0 + wm*64 + mf*16 + g;
        #pragma unroll
        for (int nf = 0; nf < 4; nf++) {
            int ccol = wn*32 + nf*8 + 2*tg;
            size_t i0 = ((size_t)bh*TT + r)*HD + ccol;
            size_t i1 = ((size_t)bh*TT + r + 8)*HD + ccol;
            __half2 h0 = h2hi(acc[mf][nf][0], acc[mf][nf][1]);
            __half2 h1 = h2hi(acc[mf][nf][2], acc[mf][nf][3]);
            *(__half2*)(g_oh + i0) = h0;
            *(__half2*)(g_ol + i0) = h2lo(acc[mf][nf][0], acc[mf][nf][1], h0);
            *(__half2*)(g_oh + i1) = h1;
            *(__half2*)(g_ol + i1) = h2lo(acc[mf][nf][2], acc[mf][nf][3], h1);
        }
    }
}

// ---------------- K4: out = O @ W_out + b ----------------
__global__ __launch_bounds__(256, 2) void k_outproj(const float* __restrict__ bout,
                                                    float* __restrict__ out) {
    extern __shared__ __half sm[];
    __half* Ah = sm;
    __half* Al = sm + 5120;
    __half* Bh = sm + 10240;
    const int tid = threadIdx.x, lane = tid & 31, wid = tid >> 5;
    const int wm = wid & 1, wn = wid >> 1, g = lane >> 2, tg = lane & 3;
    const int bn = blockIdx.x * 128, bm = blockIdx.y * 128;
    const int l15 = lane & 15;

    float acc[4][4][4] = {};
    const uint32_t aBaseH = s2u(Ah) + (((wm*64 + l15) * STR32 + (lane >> 4) * 8) << 1);
    const uint32_t aBaseL = aBaseH + 5120 * 2;
    const uint32_t bBase  = s2u(Bh) + (((wn*32 + (l15 & 7)) * STR32 + (l15 >> 3) * 8) << 1);

    for (int c = 0; c < 32; c++) {
        #pragma unroll
        for (int i = 0; i < 2; i++) {
            int f = tid + i*256, row = f >> 2, c8 = f & 3;
            int m = bm + row, b = m >> 11, t = m & 2047;
            int kk = c*32 + c8*8, hh = kk >> 6, dd = kk & 63;
            size_t go = ((size_t)(b*HH + hh)*TT + t)*HD + dd;
            *(uint4*)(Ah + row*STR32 + c8*8) = *(const uint4*)(g_oh + go);
            *(uint4*)(Al + row*STR32 + c8*8) = *(const uint4*)(g_ol + go);
            *(uint4*)(Bh + row*STR32 + c8*8) = *(const uint4*)(g_woutTh + (size_t)(bn+row)*CC + c*32 + c8*8);
        }
        __syncthreads();
        #pragma unroll
        for (int ks = 0; ks < 2; ks++) {
            uint32_t ah[4][4], al[4][4], bf[4][2];
            #pragma unroll
            for (int mf = 0; mf < 4; mf++) {
                uint32_t off = (uint32_t)((mf*16*STR32 + ks*16) << 1);
                ldm4(ah[mf], aBaseH + off);
                ldm4(al[mf], aBaseL + off);
            }
            #pragma unroll
            for (int nf = 0; nf < 4; nf++)
                ldm2(bf[nf], bBase + (uint32_t)((nf*8*STR32 + ks*16) << 1));
            #pragma unroll
            for (int nf = 0; nf < 4; nf++)
                #pragma unroll
                for (int mf = 0; mf < 4; mf++) {
                    mma16816(acc[mf][nf], ah[mf], bf[nf][0], bf[nf][1]);
                    mma16816(acc[mf][nf], al[mf], bf[nf][0], bf[nf][1]);
                }
        }
        __syncthreads();
    }
    #pragma unroll
    for (int mf = 0; mf < 4; mf++) {
        #pragma unroll
        for (int half = 0; half < 2; half++) {
            int m = bm + wm*64 + mf*16 + g + half*8;
            #pragma unroll
            for (int nf = 0; nf < 4; nf++) {
                int n = bn + wn*32 + nf*8 + 2*tg;
                float2 o = make_float2(acc[mf][nf][half*2+0] + bout[n],
                                       acc[mf][nf][half*2+1] + bout[n+1]);
                *(float2*)(out + (size_t)m*CC + n) = o;
            }
        }
    }
}

// ---------------- launch ----------------
extern "C" void kernel_launch(void* const* d_in, const int* in_sizes, int n_in,
                              void* d_out, int out_size) {
    const float* x    = (const float*)d_in[0];
    const float* Wqkv = (const float*)d_in[1];
    const float* Wout = (const float*)d_in[2];
    const float* bout = (const float*)d_in[3];
    float* out  = (float*)d_out;
    float* attn = out + (size_t)BB * TT * CC;

    cudaFuncSetAttribute(k_scores, cudaFuncAttributeMaxDynamicSharedMemorySize, 57344);
    cudaFuncSetAttribute(k_pv,     cudaFuncAttributeMaxDynamicSharedMemorySize, 47104);

    k_rope_tab<<<256, 256>>>();
    k_half_x<<<(BB*TT*CC)/1024, 256>>>(x);
    k_transpose<<<dim3(C3 / 32, CC / 32), dim3(32, 8)>>>(Wqkv, 0, CC, C3);
    k_transpose<<<dim3(CC / 32, CC / 32), dim3(32, 8)>>>(Wout, 1, CC, CC);
    k_qkv    <<<dim3(C3 / 128, (BB * TT) / 128), 256, 30720>>>();
    k_scores <<<dim3(TT / 128, NBH), 256, 57344>>>(attn);
    k_pv     <<<dim3(TT / 256, NBH), 256, 47104>>>(attn);
    k_outproj<<<dim3(CC / 128, (BB * TT) / 128), 256, 30720>>>(bout, out);
}

// round 12
// speedup vs baseline: 2.8804x; 1.0567x over previous
#include <cuda_runtime.h>
#include <cuda_fp16.h>
#include <cstdint>
#include <math.h>

#define BB 2
#define TT 2048
#define CC 1024
#define HH 16
#define HD 64
#define NBH 32
#define C3 3072

// ---------------- device scratch (never passed as kernel args) ----------------
__device__ __half g_xh[BB*TT*CC];
__device__ __half g_xl[BB*TT*CC];
__device__ __half g_wqkvTh[C3*CC];      // [n][k] hi
__device__ __half g_woutTh[CC*CC];      // [n][k] hi
__device__ __half g_qh[NBH*TT*HD];      // [bh][t][d]
__device__ __half g_ql[NBH*TT*HD];
__device__ __half g_kh[NBH*TT*HD];
__device__ __half g_vth[NBH*HD*TT];     // [bh][d][t]
__device__ __half g_oh[NBH*TT*HD];
__device__ __half g_ol[NBH*TT*HD];
__device__ float g_rinv[NBH*TT];
__device__ float g_cos[TT*32];
__device__ float g_sin[TT*32];

#define STR32 40
#define STR64 72

// ---------------- helpers ----------------
__device__ __forceinline__ uint32_t s2u(const void* p) {
    uint32_t a;
    asm("{ .reg .u64 t; cvta.to.shared.u64 t, %1; cvt.u32.u64 %0, t; }" : "=r"(a) : "l"(p));
    return a;
}
#define CPA16(sa, gp) asm volatile("cp.async.cg.shared.global [%0], [%1], 16;" :: "r"(sa), "l"(gp) : "memory")
#define CPA_COMMIT()  asm volatile("cp.async.commit_group;" ::: "memory")
#define CPA_WAIT1()   asm volatile("cp.async.wait_group 1;" ::: "memory")
#define CPA_WAIT0()   asm volatile("cp.async.wait_group 0;" ::: "memory")

__device__ __forceinline__ void mma16816(float* d, const uint32_t* a, uint32_t b0, uint32_t b1) {
    asm volatile("mma.sync.aligned.m16n8k16.row.col.f32.f16.f16.f32 "
                 "{%0,%1,%2,%3}, {%4,%5,%6,%7}, {%8,%9}, {%0,%1,%2,%3};"
                 : "+f"(d[0]), "+f"(d[1]), "+f"(d[2]), "+f"(d[3])
                 : "r"(a[0]), "r"(a[1]), "r"(a[2]), "r"(a[3]), "r"(b0), "r"(b1));
}
__device__ __forceinline__ void ldm4(uint32_t* r, uint32_t a) {
    asm volatile("ldmatrix.sync.aligned.m8n8.x4.shared.b16 {%0,%1,%2,%3}, [%4];"
                 : "=r"(r[0]), "=r"(r[1]), "=r"(r[2]), "=r"(r[3]) : "r"(a));
}
__device__ __forceinline__ void ldm2(uint32_t* r, uint32_t a) {
    asm volatile("ldmatrix.sync.aligned.m8n8.x2.shared.b16 {%0,%1}, [%2];"
                 : "=r"(r[0]), "=r"(r[1]) : "r"(a));
}
__device__ __forceinline__ __half2 h2hi(float a, float b) {
    return __halves2half2(__float2half_rn(a), __float2half_rn(b));
}
__device__ __forceinline__ __half2 h2lo(float a, float b, __half2 h) {
    return __halves2half2(__float2half_rn(a - __low2float(h)),
                          __float2half_rn(b - __high2float(h)));
}
__device__ __forceinline__ void splitst(__half* hi, __half* lo, int idx, float4 v) {
    __half2 H0 = h2hi(v.x, v.y), H1 = h2hi(v.z, v.w);
    __half2 L0 = h2lo(v.x, v.y, H0), L1 = h2lo(v.z, v.w, H1);
    uint2 HU, LU;
    HU.x = *reinterpret_cast<uint32_t*>(&H0); HU.y = *reinterpret_cast<uint32_t*>(&H1);
    LU.x = *reinterpret_cast<uint32_t*>(&L0); LU.y = *reinterpret_cast<uint32_t*>(&L1);
    *reinterpret_cast<uint2*>(hi + idx) = HU;
    *reinterpret_cast<uint2*>(lo + idx) = LU;
}

// ---------------- RoPE table ----------------
__global__ void k_rope_tab() {
    int idx = blockIdx.x * 256 + threadIdx.x;
    if (idx >= TT * 32) return;
    int t = idx / 32, j = idx % 32;
    int mi = (2 * j) % 32;
    float inv32 = (float)pow(10000.0, -(double)mi / 32.0);
    float th32 = (float)t * inv32;
    g_cos[idx] = (float)cos((double)th32);
    g_sin[idx] = (float)sin((double)th32);
}

// ---------------- split x into fp16 hi/lo ----------------
__global__ void k_half_x(const float* __restrict__ x) {
    int idx = (blockIdx.x * 256 + threadIdx.x) * 4;
    float4 v = *(const float4*)(x + idx);
    __half2 H0 = h2hi(v.x, v.y), H1 = h2hi(v.z, v.w);
    __half2 L0 = h2lo(v.x, v.y, H0), L1 = h2lo(v.z, v.w, H1);
    uint2 HU, LU;
    HU.x = *reinterpret_cast<uint32_t*>(&H0); HU.y = *reinterpret_cast<uint32_t*>(&H1);
    LU.x = *reinterpret_cast<uint32_t*>(&L0); LU.y = *reinterpret_cast<uint32_t*>(&L1);
    *reinterpret_cast<uint2*>(g_xh + idx) = HU;
    *reinterpret_cast<uint2*>(g_xl + idx) = LU;
}

// ---------------- transpose + fp16 convert: src[K][N] -> dst[N][K] ----------------
__global__ void k_transpose(const float* __restrict__ src, int which, int K, int N) {
    __shared__ float tb[32][33];
    __half* dst = which ? g_woutTh : g_wqkvTh;
    int n0 = blockIdx.x * 32, k0 = blockIdx.y * 32;
    for (int i = threadIdx.y; i < 32; i += 8)
        tb[i][threadIdx.x] = src[(size_t)(k0 + i) * N + n0 + threadIdx.x];
    __syncthreads();
    for (int i = threadIdx.y; i < 32; i += 8)
        dst[(size_t)(n0 + i) * K + k0 + threadIdx.x] = __float2half_rn(tb[threadIdx.x][i]);
}

// ---------------- K1: QKV GEMM (HMMA 2-pass, cp.async double-buffer) ----------------
#define QKV_STAGE 15360    // halves per stage: Ah 5120 + Al 5120 + Bh 5120
__global__ __launch_bounds__(256, 2) void k_qkv() {
    extern __shared__ __half sm[];
    const int tid = threadIdx.x, lane = tid & 31, wid = tid >> 5;
    const int wm = wid & 1, wn = wid >> 1, g = lane >> 2, tg = lane & 3;
    const int bn = blockIdx.x * 128, bm = blockIdx.y * 128;
    const int l15 = lane & 15;
    const uint32_t su = s2u(sm);

    // per-thread fill coordinates (2 rows of 8 halves each per tile)
    const int fr0 = tid >> 2, fc0 = tid & 3;              // rows 0..63
    const int fr1 = fr0 + 64, fc1 = fc0;                  // rows 64..127

    float acc[4][4][4] = {};
    const uint32_t aOffH = (uint32_t)(((wm*64 + l15) * STR32 + (lane >> 4) * 8) << 1);
    const uint32_t aOffL = aOffH + 5120 * 2;
    const uint32_t bOff  = (uint32_t)((10240 + (wn*32 + (l15 & 7)) * STR32 + (l15 >> 3) * 8) << 1);

    // fill chunk c into stage s
    auto fill = [&](int c, int s) {
        uint32_t sb = su + (uint32_t)((s * QKV_STAGE) << 1);
        size_t gA0 = (size_t)(bm+fr0)*CC + c*32 + fc0*8;
        size_t gA1 = (size_t)(bm+fr1)*CC + c*32 + fc1*8;
        CPA16(sb + (uint32_t)((fr0*STR32 + fc0*8) << 1),          g_xh + gA0);
        CPA16(sb + (uint32_t)((fr1*STR32 + fc1*8) << 1),          g_xh + gA1);
        CPA16(sb + (uint32_t)((5120 + fr0*STR32 + fc0*8) << 1),   g_xl + gA0);
        CPA16(sb + (uint32_t)((5120 + fr1*STR32 + fc1*8) << 1),   g_xl + gA1);
        CPA16(sb + (uint32_t)((10240 + fr0*STR32 + fc0*8) << 1),  g_wqkvTh + (size_t)(bn+fr0)*CC + c*32 + fc0*8);
        CPA16(sb + (uint32_t)((10240 + fr1*STR32 + fc1*8) << 1),  g_wqkvTh + (size_t)(bn+fr1)*CC + c*32 + fc1*8);
    };

    fill(0, 0); CPA_COMMIT();
    for (int c = 0; c < 32; c++) {
        int s = c & 1;
        if (c < 31) { fill(c+1, s^1); CPA_COMMIT(); CPA_WAIT1(); }
        else CPA_WAIT0();
        __syncthreads();
        uint32_t stb = su + (uint32_t)((s * QKV_STAGE) << 1);
        #pragma unroll
        for (int ks = 0; ks < 2; ks++) {
            uint32_t ah[4][4], al[4][4], bf[4][2];
            #pragma unroll
            for (int mf = 0; mf < 4; mf++) {
                uint32_t off = (uint32_t)((mf*16*STR32 + ks*16) << 1);
                ldm4(ah[mf], stb + aOffH + off);
                ldm4(al[mf], stb + aOffL + off);
            }
            #pragma unroll
            for (int nf = 0; nf < 4; nf++)
                ldm2(bf[nf], stb + bOff + (uint32_t)((nf*8*STR32 + ks*16) << 1));
            #pragma unroll
            for (int nf = 0; nf < 4; nf++)
                #pragma unroll
                for (int mf = 0; mf < 4; mf++) {
                    mma16816(acc[mf][nf], ah[mf], bf[nf][0], bf[nf][1]);
                    mma16816(acc[mf][nf], al[mf], bf[nf][0], bf[nf][1]);
                }
        }
        __syncthreads();
    }
    #pragma unroll
    for (int mf = 0; mf < 4; mf++) {
        #pragma unroll
        for (int half = 0; half < 2; half++) {
            int m = bm + wm*64 + mf*16 + g + half*8;
            int b = m >> 11, t = m & 2047;
            #pragma unroll
            for (int nf = 0; nf < 4; nf++) {
                int n = bn + wn*32 + nf*8 + 2*tg;
                float v0 = acc[mf][nf][half*2 + 0], v1 = acc[mf][nf][half*2 + 1];
                int sect = n >> 10, rem = n & 1023, hh = rem >> 6, d = rem & 63;
                if (sect == 2) {
                    size_t base = ((size_t)(b*HH + hh) * HD + d) * TT + t;
                    g_vth[base] = __float2half_rn(v0);
                    g_vth[base + TT] = __float2half_rn(v1);
                } else {
                    int j2 = d >> 1;
                    float cs = g_cos[t*32 + j2], sn = g_sin[t*32 + j2];
                    float r0 = v0*cs - v1*sn, r1 = v1*cs + v0*sn;
                    size_t idx = ((size_t)(b*HH + hh)*TT + t)*HD + d;
                    __half2 hi = h2hi(r0, r1);
                    if (sect == 0) {
                        *(__half2*)(g_qh + idx) = hi;
                        *(__half2*)(g_ql + idx) = h2lo(r0, r1, hi);
                    } else {
                        *(__half2*)(g_kh + idx) = hi;
                    }
                }
            }
        }
    }
}

// ---------------- K2: attn <- exp(QK^T/8 - alibi); g_rinv <- 1/rowsum -------------
// smem: Qh 9216 | Ql 9216 | Kh stage0 9216 | Kh stage1 9216 | srd 512 floats
__global__ __launch_bounds__(256, 2) void k_scores(float* __restrict__ attn) {
    extern __shared__ __half sm[];
    __half* Qh = sm;
    __half* Ql = sm + 9216;
    float* srd_s = (float*)(sm + 36864);   // [4][128]
    const int tid = threadIdx.x, lane = tid & 31, wid = tid >> 5;
    const int wm = wid & 1, wn = wid >> 1, g = lane >> 2, tg = lane & 3;
    const int bh = blockIdx.y, h = bh & 15, q0 = blockIdx.x * 128;
    const int l15 = lane & 15;
    const uint32_t su = s2u(sm);
    const __half* qhb = g_qh + (size_t)bh * TT * HD;
    const __half* qlb = g_ql + (size_t)bh * TT * HD;
    const __half* khb = g_kh + (size_t)bh * TT * HD;

    #pragma unroll
    for (int i = 0; i < 4; i++) {
        int f = tid + i*256, row = f >> 3, c8 = f & 7;
        size_t go = (size_t)(q0+row)*HD + c8*8;
        *(uint4*)(Qh + row*STR64 + c8*8) = *(const uint4*)(qhb + go);
        *(uint4*)(Ql + row*STR64 + c8*8) = *(const uint4*)(qlb + go);
    }
    const uint32_t aBaseH = su + (uint32_t)(((wm*64 + l15) * STR64 + (lane >> 4) * 8) << 1);
    const uint32_t aBaseL = aBaseH + 9216 * 2;
    const uint32_t bOff   = (uint32_t)(((wn*32 + (l15 & 7)) * STR64 + (l15 >> 3) * 8) << 1);
    const float slope = exp2f(-0.5f * (float)(h + 1));
    float rs[8];
    #pragma unroll
    for (int i = 0; i < 8; i++) rs[i] = 0.f;

    const int fr = tid >> 1, fc = tid & 1;     // 128 rows x 2 chunks of 8... wait 128*8=1024 halves/row? no
    // K tile: 128 rows x 64 halves = 8192 halves = 1024 x 16B chunks; 256 thr -> 4 chunks each
    auto fillK = [&](int nt, int s) {
        uint32_t sb = su + (uint32_t)(((18432 + s*9216)) << 1);
        #pragma unroll
        for (int i = 0; i < 4; i++) {
            int f = tid + i*256, row = f >> 3, c8 = f & 7;
            CPA16(sb + (uint32_t)((row*STR64 + c8*8) << 1),
                  khb + (size_t)(nt*128+row)*HD + c8*8);
        }
    };

    fillK(0, 0); CPA_COMMIT();
    for (int nt = 0; nt < 16; nt++) {
        int s = nt & 1;
        if (nt < 15) { fillK(nt+1, s^1); CPA_COMMIT(); CPA_WAIT1(); }
        else CPA_WAIT0();
        __syncthreads();
        uint32_t bBase = su + (uint32_t)((18432 + s*9216) << 1) + bOff;
        float acc[4][4][4] = {};
        #pragma unroll
        for (int ks = 0; ks < 4; ks++) {
            uint32_t ah[4][4], al[4][4], bf[4][2];
            #pragma unroll
            for (int mf = 0; mf < 4; mf++) {
                uint32_t off = (uint32_t)((mf*16*STR64 + ks*16) << 1);
                ldm4(ah[mf], aBaseH + off);
                ldm4(al[mf], aBaseL + off);
            }
            #pragma unroll
            for (int nf = 0; nf < 4; nf++)
                ldm2(bf[nf], bBase + (uint32_t)((nf*8*STR64 + ks*16) << 1));
            #pragma unroll
            for (int nf = 0; nf < 4; nf++)
                #pragma unroll
                for (int mf = 0; mf < 4; mf++) {
                    mma16816(acc[mf][nf], ah[mf], bf[nf][0], bf[nf][1]);
                    mma16816(acc[mf][nf], al[mf], bf[nf][0], bf[nf][1]);
                }
        }
        #pragma unroll
        for (int mf = 0; mf < 4; mf++) {
            #pragma unroll
            for (int half = 0; half < 2; half++) {
                int r = wm*64 + mf*16 + g + half*8;
                int q = q0 + r;
                float ssum = 0.f;
                #pragma unroll
                for (int nf = 0; nf < 4; nf++) {
                    int col = nt*128 + wn*32 + nf*8 + 2*tg;
                    float e0 = __expf(acc[mf][nf][half*2+0] * 0.125f - slope * fabsf((float)(q - col)));
                    float e1 = __expf(acc[mf][nf][half*2+1] * 0.125f - slope * fabsf((float)(q - col - 1)));
                    *(float2*)(attn + ((size_t)bh*TT + q)*TT + col) = make_float2(e0, e1);
                    ssum += e0 + e1;
                }
                rs[mf*2 + half] += ssum;
            }
        }
        __syncthreads();
    }
    #pragma unroll
    for (int i = 0; i < 8; i++) {
        rs[i] += __shfl_xor_sync(0xffffffffu, rs[i], 1);
        rs[i] += __shfl_xor_sync(0xffffffffu, rs[i], 2);
    }
    if (tg == 0) {
        #pragma unroll
        for (int mf = 0; mf < 4; mf++)
            #pragma unroll
            for (int half = 0; half < 2; half++) {
                int r = wm*64 + mf*16 + g + half*8;
                srd_s[wn*128 + r] = rs[mf*2 + half];
            }
    }
    __syncthreads();
    if (tid < 128) {
        float s = srd_s[tid] + srd_s[128 + tid] + srd_s[256 + tid] + srd_s[384 + tid];
        g_rinv[(size_t)bh*TT + q0 + tid] = 1.0f / s;
    }
}

// ---------------- K3: P = E * rinv (final attn) + O = P @ V ----------------
__global__ __launch_bounds__(256, 2) void k_pv(float* __restrict__ attn) {
    extern __shared__ __half sm[];
    __half* Ph = sm;              // 256*40
    __half* Pl = sm + 10240;
    __half* Vh = sm + 20480;      // 64*40
    float* sri = (float*)(sm + 23040);   // 256
    const int tid = threadIdx.x, lane = tid & 31, wid = tid >> 5;
    const int wm = wid & 3, wn = wid >> 2, g = lane >> 2, tg = lane & 3;
    const int bh = blockIdx.y, q0 = blockIdx.x * 256;
    const int l15 = lane & 15;
    sri[tid] = g_rinv[(size_t)bh*TT + q0 + tid];
    __syncthreads();
    float acc[4][4][4] = {};
    const uint32_t aBaseH = s2u(Ph) + (((wm*64 + l15) * STR32 + (lane >> 4) * 8) << 1);
    const uint32_t aBaseL = aBaseH + 10240 * 2;
    const uint32_t bBase  = s2u(Vh) + (((wn*32 + (l15 & 7)) * STR32 + (l15 >> 3) * 8) << 1);
    const __half* vtb = g_vth + (size_t)bh * HD * TT;

    for (int c = 0; c < 64; c++) {
        #pragma unroll
        for (int i = 0; i < 8; i++) {
            int f = tid + i*256, row = f >> 3, c4 = f & 7;
            size_t off = ((size_t)bh*TT + q0 + row)*TT + c*32 + c4*4;
            float4 v = *(const float4*)(attn + off);
            float iv = sri[row];
            float4 p;
            p.x = v.x * iv;
            p.y = v.y * iv;
            p.z = v.z * iv;
            p.w = v.w * iv;
            *(float4*)(attn + off) = p;               // final attn output
            splitst(Ph, Pl, row*STR32 + c4*4, p);
        }
        {
            int row = tid >> 2, c8 = tid & 3;
            *(uint4*)(Vh + row*STR32 + c8*8) = *(const uint4*)(vtb + (size_t)row*TT + c*32 + c8*8);
        }
        __syncthreads();
        #pragma unroll
        for (int ks = 0; ks < 2; ks++) {
            uint32_t ah[4][4], al[4][4], bf[4][2];
            #pragma unroll
            for (int mf = 0; mf < 4; mf++) {
                uint32_t off = (uint32_t)((mf*16*STR32 + ks*16) << 1);
                ldm4(ah[mf], aBaseH + off);
                ldm4(al[mf], aBaseL + off);
            }
            #pragma unroll
            for (int nf = 0; nf < 4; nf++)
                ldm2(bf[nf], bBase + (uint32_t)((nf*8*STR32 + ks*16) << 1));
            #pragma unroll
            for (int nf = 0; nf < 4; nf++)
                #pragma unroll
                for (int mf = 0; mf < 4; mf++) {
                    mma16816(acc[mf][nf], ah[mf], bf[nf][0], bf[nf][1]);
                    mma16816(acc[mf][nf], al[mf], bf[nf][0], bf[nf][1]);
                }
        }
        __syncthreads();
    }
    #pragma unroll
    for (int mf = 0; mf < 4; mf++) {
        int r = q0 + wm*64 + mf*16 + g;
        #pragma unroll
        for (int nf = 0; nf < 4; nf++) {
            int ccol = wn*32 + nf*8 + 2*tg;
            size_t i0 = ((size_t)bh*TT + r)*HD + ccol;
            size_t i1 = ((size_t)bh*TT + r + 8)*HD + ccol;
            __half2 h0 = h2hi(acc[mf][nf][0], acc[mf][nf][1]);
            __half2 h1 = h2hi(acc[mf][nf][2], acc[mf][nf][3]);
            *(__half2*)(g_oh + i0) = h0;
            *(__half2*)(g_ol + i0) = h2lo(acc[mf][nf][0], acc[mf][nf][1], h0);
            *(__half2*)(g_oh + i1) = h1;
            *(__half2*)(g_ol + i1) = h2lo(acc[mf][nf][2], acc[mf][nf][3], h1);
        }
    }
}

// ---------------- K4: out = O @ W_out + b (cp.async double-buffer) ----------------
__global__ __launch_bounds__(256, 2) void k_outproj(const float* __restrict__ bout,
                                                    float* __restrict__ out) {
    extern __shared__ __half sm[];
    const int tid = threadIdx.x, lane = tid & 31, wid = tid >> 5;
    const int wm = wid & 1, wn = wid >> 1, g = lane >> 2, tg = lane & 3;
    const int bn = blockIdx.x * 128, bm = blockIdx.y * 128;
    const int l15 = lane & 15;
    const uint32_t su = s2u(sm);
    const int fr0 = tid >> 2, fc0 = tid & 3;
    const int fr1 = fr0 + 64;

    float acc[4][4][4] = {};
    const uint32_t aOffH = (uint32_t)(((wm*64 + l15) * STR32 + (lane >> 4) * 8) << 1);
    const uint32_t aOffL = aOffH + 5120 * 2;
    const uint32_t bOff  = (uint32_t)((10240 + (wn*32 + (l15 & 7)) * STR32 + (l15 >> 3) * 8) << 1);

    auto fill = [&](int c, int s) {
        uint32_t sb = su + (uint32_t)((s * QKV_STAGE) << 1);
        #pragma unroll
        for (int half = 0; half < 2; half++) {
            int row = half ? fr1 : fr0, c8 = fc0;
            int m = bm + row, b = m >> 11, t = m & 2047;
            int kk = c*32 + c8*8, hh = kk >> 6, dd = kk & 63;
            size_t go = ((size_t)(b*HH + hh)*TT + t)*HD + dd;
            CPA16(sb + (uint32_t)((row*STR32 + c8*8) << 1),         g_oh + go);
            CPA16(sb + (uint32_t)((5120 + row*STR32 + c8*8) << 1),  g_ol + go);
            CPA16(sb + (uint32_t)((10240 + row*STR32 + c8*8) << 1), g_woutTh + (size_t)(bn+row)*CC + c*32 + c8*8);
        }
    };

    fill(0, 0); CPA_COMMIT();
    for (int c = 0; c < 32; c++) {
        int s = c & 1;
        if (c < 31) { fill(c+1, s^1); CPA_COMMIT(); CPA_WAIT1(); }
        else CPA_WAIT0();
        __syncthreads();
        uint32_t stb = su + (uint32_t)((s * QKV_STAGE) << 1);
        #pragma unroll
        for (int ks = 0; ks < 2; ks++) {
            uint32_t ah[4][4], al[4][4], bf[4][2];
            #pragma unroll
            for (int mf = 0; mf < 4; mf++) {
                uint32_t off = (uint32_t)((mf*16*STR32 + ks*16) << 1);
                ldm4(ah[mf], stb + aOffH + off);
                ldm4(al[mf], stb + aOffL + off);
            }
            #pragma unroll
            for (int nf = 0; nf < 4; nf++)
                ldm2(bf[nf], stb + bOff + (uint32_t)((nf*8*STR32 + ks*16) << 1));
            #pragma unroll
            for (int nf = 0; nf < 4; nf++)
                #pragma unroll
                for (int mf = 0; mf < 4; mf++) {
                    mma16816(acc[mf][nf], ah[mf], bf[nf][0], bf[nf][1]);
                    mma16816(acc[mf][nf], al[mf], bf[nf][0], bf[nf][1]);
                }
        }
        __syncthreads();
    }
    #pragma unroll
    for (int mf = 0; mf < 4; mf++) {
        #pragma unroll
        for (int half = 0; half < 2; half++) {
            int m = bm + wm*64 + mf*16 + g + half*8;
            #pragma unroll
            for (int nf = 0; nf < 4; nf++) {
                int n = bn + wn*32 + nf*8 + 2*tg;
                float2 o = make_float2(acc[mf][nf][half*2+0] + bout[n],
                                       acc[mf][nf][half*2+1] + bout[n+1]);
                *(float2*)(out + (size_t)m*CC + n) = o;
            }
        }
    }
}

// ---------------- launch ----------------
extern "C" void kernel_launch(void* const* d_in, const int* in_sizes, int n_in,
                              void* d_out, int out_size) {
    const float* x    = (const float*)d_in[0];
    const float* Wqkv = (const float*)d_in[1];
    const float* Wout = (const float*)d_in[2];
    const float* bout = (const float*)d_in[3];
    float* out  = (float*)d_out;
    float* attn = out + (size_t)BB * TT * CC;

    cudaFuncSetAttribute(k_qkv,     cudaFuncAttributeMaxDynamicSharedMemorySize, 61440);
    cudaFuncSetAttribute(k_scores,  cudaFuncAttributeMaxDynamicSharedMemorySize, 75776);
    cudaFuncSetAttribute(k_pv,      cudaFuncAttributeMaxDynamicSharedMemorySize, 47104);
    cudaFuncSetAttribute(k_outproj, cudaFuncAttributeMaxDynamicSharedMemorySize, 61440);

    k_rope_tab<<<256, 256>>>();
    k_half_x<<<(BB*TT*CC)/1024, 256>>>(x);
    k_transpose<<<dim3(C3 / 32, CC / 32), dim3(32, 8)>>>(Wqkv, 0, CC, C3);
    k_transpose<<<dim3(CC / 32, CC / 32), dim3(32, 8)>>>(Wout, 1, CC, CC);
    k_qkv    <<<dim3(C3 / 128, (BB * TT) / 128), 256, 61440>>>();
    k_scores <<<dim3(TT / 128, NBH), 256, 75776>>>(attn);
    k_pv     <<<dim3(TT / 256, NBH), 256, 47104>>>(attn);
    k_outproj<<<dim3(CC / 128, (BB * TT) / 128), 256, 61440>>>(bout, out);
}